// round 1
// baseline (speedup 1.0000x reference)
#include <cuda_runtime.h>

#define NN 100000
#define EE 1600000
#define IN_DIM 128
#define HD 64

// Scratch (device globals: no allocation allowed)
__device__ float g_deg[NN];
__device__ float g_dinv[NN];
__device__ float g_h[NN * HD];
__device__ float g_agg[NN * HD];
__device__ float g_B[NN * HD];

// ---------------------------------------------------------------------------
// Zero scratch accumulators (graph-capturable, deterministic)
__global__ void zero_kernel() {
    int idx = blockIdx.x * blockDim.x + threadIdx.x;
    if (idx < NN * HD / 4) {
        ((float4*)g_agg)[idx] = make_float4(0.f, 0.f, 0.f, 0.f);
        ((float4*)g_B)[idx]   = make_float4(0.f, 0.f, 0.f, 0.f);
    }
    if (idx < NN) g_deg[idx] = 0.f;
}

// ---------------------------------------------------------------------------
__global__ void deg_kernel(const int* __restrict__ dst) {
    int e = blockIdx.x * 256 + threadIdx.x;
    if (e < EE) {
        float* p = g_deg + dst[e];
        asm volatile("red.global.add.f32 [%0], %1;" :: "l"(p), "f"(1.0f) : "memory");
    }
}

__global__ void dinv_kernel() {
    int n = blockIdx.x * 256 + threadIdx.x;
    if (n < NN) {
        float d = fmaxf(g_deg[n], 1.0f);
        g_dinv[n] = rsqrtf(d);
    }
}

// ---------------------------------------------------------------------------
// Fused 2-layer MLP: h = relu(relu(X @ W1^T + b1) @ W2^T + b2)
// Block: 256 threads = 64 output cols x 4 groups; 32 rows/block, 8 rows/thread.
#define MLP_SMEM_FLOATS (128*65 + 64*65 + 32*128 + 32*64 + 64 + 64)
__global__ void mlp_kernel(const float* __restrict__ X, const float* __restrict__ W1,
                           const float* __restrict__ b1, const float* __restrict__ W2,
                           const float* __restrict__ b2) {
    extern __shared__ float sm[];
    float* sW1T = sm;                   // [128][65] transposed, padded
    float* sW2T = sW1T + 128 * 65;      // [64][65]
    float* sX   = sW2T + 64 * 65;       // [32][128]
    float* sT   = sX + 32 * 128;        // [32][64]
    float* sb1  = sT + 32 * 64;
    float* sb2  = sb1 + 64;

    int tid = threadIdx.x;
    for (int idx = tid; idx < 64 * 128; idx += 256) {
        int j = idx >> 7, k = idx & 127;
        sW1T[k * 65 + j] = W1[idx];
    }
    for (int idx = tid; idx < 64 * 64; idx += 256) {
        int j = idx >> 6, k = idx & 63;
        sW2T[k * 65 + j] = W2[idx];
    }
    int rowbase = blockIdx.x * 32;
    for (int idx = tid; idx < 32 * 128; idx += 256)
        sX[idx] = X[rowbase * 128 + idx];
    if (tid < 64) { sb1[tid] = b1[tid]; sb2[tid] = b2[tid]; }
    __syncthreads();

    int j = tid & 63, g = tid >> 6;
    float acc[8];
#pragma unroll
    for (int r = 0; r < 8; r++) acc[r] = sb1[j];
    for (int k = 0; k < 128; k++) {
        float w = sW1T[k * 65 + j];
#pragma unroll
        for (int r = 0; r < 8; r++) acc[r] += w * sX[(g * 8 + r) * 128 + k];
    }
#pragma unroll
    for (int r = 0; r < 8; r++) sT[(g * 8 + r) * 64 + j] = fmaxf(acc[r], 0.f);
    __syncthreads();

#pragma unroll
    for (int r = 0; r < 8; r++) acc[r] = sb2[j];
    for (int k = 0; k < 64; k++) {
        float w = sW2T[k * 65 + j];
#pragma unroll
        for (int r = 0; r < 8; r++) acc[r] += w * sT[(g * 8 + r) * 64 + k];
    }
#pragma unroll
    for (int r = 0; r < 8; r++)
        g_h[(rowbase + g * 8 + r) * 64 + j] = fmaxf(acc[r], 0.f);
}

// ---------------------------------------------------------------------------
// Scatter pass 1: agg += segsum((h * dinv)[src]) over dst.
// 16 threads per edge, one float4 per thread (256B row), vectorized red.
__global__ void scatter1_kernel(const int* __restrict__ src, const int* __restrict__ dst) {
    unsigned t = blockIdx.x * 256u + threadIdx.x;
    unsigned e = t >> 4;
    int c = t & 15;
    if (e >= EE) return;
    int lane = threadIdx.x & 31;
    int s = 0, d = 0;
    if ((lane & 15) == 0) { s = src[e]; d = dst[e]; }
    s = __shfl_sync(0xffffffffu, s, lane & 16);
    d = __shfl_sync(0xffffffffu, d, lane & 16);
    float sc = g_dinv[s];
    float4 v = ((const float4*)g_h)[s * 16 + c];
    v.x *= sc; v.y *= sc; v.z *= sc; v.w *= sc;
    float4* p = ((float4*)g_agg) + d * 16 + c;
    asm volatile("red.global.add.v4.f32 [%0], {%1,%2,%3,%4};"
                 :: "l"(p), "f"(v.x), "f"(v.y), "f"(v.z), "f"(v.w) : "memory");
}

// Scatter pass 2: B += segsum((agg * dinv^2)[src]) over dst.
__global__ void scatter2_kernel(const int* __restrict__ src, const int* __restrict__ dst) {
    unsigned t = blockIdx.x * 256u + threadIdx.x;
    unsigned e = t >> 4;
    int c = t & 15;
    if (e >= EE) return;
    int lane = threadIdx.x & 31;
    int s = 0, d = 0;
    if ((lane & 15) == 0) { s = src[e]; d = dst[e]; }
    s = __shfl_sync(0xffffffffu, s, lane & 16);
    d = __shfl_sync(0xffffffffu, d, lane & 16);
    float di = g_dinv[s];
    float sc = di * di;
    float4 v = ((const float4*)g_agg)[s * 16 + c];
    v.x *= sc; v.y *= sc; v.z *= sc; v.w *= sc;
    float4* p = ((float4*)g_B) + d * 16 + c;
    asm volatile("red.global.add.v4.f32 [%0], {%1,%2,%3,%4};"
                 :: "l"(p), "f"(v.x), "f"(v.y), "f"(v.z), "f"(v.w) : "memory");
}

// ---------------------------------------------------------------------------
// Fused epilogue. Per node n (using shared agg1=agg, B):
//   gv = agg*dinv
//   conv i: f1_i = h - ld_i1*gv ; f2_i = f1_i - ld_i2*((agg - ld_i1*B)*dinv)
//   h1 = 3*(h*ld1_0)@cW1^T + cb1 - 3*f1_1 + 0.75*f2_1   (theta1 = (3,-3,.75))
//   h2 = cb2 + 3*f1_2 - 1.5*f2_2                        (theta2 = (0,3,-1.5))
//   h3 = cb3 + 0.75*f2_3                                (theta3 = (0,0,.75))
//   emb = relu([h1 h2 h3] @ W3^T + b3); logits = emb @ W4^T + b4
#define FIN_SMEM_FLOATS (64*65 + 192*65 + 32*64 + 32*192 + 32*65 + 9*64 + 192 + 64 + 128 + 4)
__global__ void final_kernel(const float* __restrict__ cW1, const float* __restrict__ cb1,
                             const float* __restrict__ cb2, const float* __restrict__ cb3,
                             const float* __restrict__ ld1, const float* __restrict__ ld2,
                             const float* __restrict__ ld3,
                             const float* __restrict__ W3, const float* __restrict__ b3,
                             const float* __restrict__ W4, const float* __restrict__ b4,
                             float* __restrict__ out_logits, float* __restrict__ out_emb) {
    extern __shared__ float sm[];
    float* s_cw1T = sm;                    // [64][65]
    float* s_w3T  = s_cw1T + 64 * 65;      // [192][65]
    float* s_hs   = s_w3T + 192 * 65;      // [32][64]   h * ld1_0
    float* s_hf   = s_hs + 32 * 64;        // [32][192]  concat features
    float* s_emb  = s_hf + 32 * 192;       // [32][65]   padded
    float* s_ld   = s_emb + 32 * 65;       // [9][64]
    float* s_cb   = s_ld + 9 * 64;         // [3][64]
    float* s_b3   = s_cb + 192;            // [64]
    float* s_w4   = s_b3 + 64;             // [2][64]
    float* s_b4   = s_w4 + 128;            // [2]

    int tid = threadIdx.x;
    for (int idx = tid; idx < 64 * 64; idx += 256) {
        int j = idx >> 6, k = idx & 63;
        s_cw1T[k * 65 + j] = cW1[idx];
    }
    for (int idx = tid; idx < 64 * 192; idx += 256) {
        int j = idx / 192, k = idx % 192;
        s_w3T[k * 65 + j] = W3[idx];
    }
    if (tid < 64) {
        int j = tid;
#pragma unroll
        for (int r = 0; r < 3; r++) {
            s_ld[(0 * 3 + r) * 64 + j] = ld1[r * 64 + j];
            s_ld[(1 * 3 + r) * 64 + j] = ld2[r * 64 + j];
            s_ld[(2 * 3 + r) * 64 + j] = ld3[r * 64 + j];
        }
        s_cb[j] = cb1[j]; s_cb[64 + j] = cb2[j]; s_cb[128 + j] = cb3[j];
        s_b3[j] = b3[j];
        s_w4[j] = W4[j]; s_w4[64 + j] = W4[64 + j];
    }
    if (tid < 2) s_b4[tid] = b4[tid];
    __syncthreads();

    int j = tid & 63, g = tid >> 6;
    int nodebase = blockIdx.x * 32 + g * 8;
    float e1r[8];

    // Phase 1: elementwise poly-conv parts
#pragma unroll
    for (int r = 0; r < 8; r++) {
        int n = nodebase + r;
        float hv = g_h[n * 64 + j];
        float a  = g_agg[n * 64 + j];
        float Bv = g_B[n * 64 + j];
        float di = g_dinv[n];
        float gv = a * di;
        // conv1 (3, -3, 0.75)
        float l1 = s_ld[1 * 64 + j], l2 = s_ld[2 * 64 + j];
        float f1 = hv - l1 * gv;
        float f2 = f1 - l2 * ((a - l1 * Bv) * di);
        e1r[r] = s_cb[j] - 3.f * f1 + 0.75f * f2;
        // conv2 (0, 3, -1.5)
        l1 = s_ld[4 * 64 + j]; l2 = s_ld[5 * 64 + j];
        f1 = hv - l1 * gv;
        f2 = f1 - l2 * ((a - l1 * Bv) * di);
        s_hf[(g * 8 + r) * 192 + 64 + j] = s_cb[64 + j] + 3.f * f1 - 1.5f * f2;
        // conv3 (0, 0, 0.75)
        l1 = s_ld[7 * 64 + j]; l2 = s_ld[8 * 64 + j];
        f1 = hv - l1 * gv;
        f2 = f1 - l2 * ((a - l1 * Bv) * di);
        s_hf[(g * 8 + r) * 192 + 128 + j] = s_cb[128 + j] + 0.75f * f2;
        s_hs[(g * 8 + r) * 64 + j] = hv * s_ld[0 * 64 + j];
    }
    __syncthreads();

    // Phase 2: h1 = 3*(h*ld1_0) @ cW1^T + elementwise part
    float acc[8];
#pragma unroll
    for (int r = 0; r < 8; r++) acc[r] = 0.f;
    for (int k = 0; k < 64; k++) {
        float w = s_cw1T[k * 65 + j];
#pragma unroll
        for (int r = 0; r < 8; r++) acc[r] += w * s_hs[(g * 8 + r) * 64 + k];
    }
#pragma unroll
    for (int r = 0; r < 8; r++) s_hf[(g * 8 + r) * 192 + j] = 3.f * acc[r] + e1r[r];
    __syncthreads();

    // Phase 3: emb = relu(hf @ W3^T + b3)
#pragma unroll
    for (int r = 0; r < 8; r++) acc[r] = s_b3[j];
    for (int k = 0; k < 192; k++) {
        float w = s_w3T[k * 65 + j];
#pragma unroll
        for (int r = 0; r < 8; r++) acc[r] += w * s_hf[(g * 8 + r) * 192 + k];
    }
#pragma unroll
    for (int r = 0; r < 8; r++) {
        float em = fmaxf(acc[r], 0.f);
        s_emb[(g * 8 + r) * 65 + j] = em;
        out_emb[(nodebase + r) * 64 + j] = em;
    }
    __syncthreads();

    // Phase 4: logits = emb @ W4^T + b4
    if (tid < 64) {
        int nl = tid >> 1, c = tid & 1;
        float a2 = s_b4[c];
        for (int k = 0; k < 64; k++) a2 += s_w4[c * 64 + k] * s_emb[nl * 65 + k];
        out_logits[(blockIdx.x * 32 + nl) * 2 + c] = a2;
    }
}

// ---------------------------------------------------------------------------
extern "C" void kernel_launch(void* const* d_in, const int* in_sizes, int n_in,
                              void* d_out, int out_size) {
    const float* in_feat = (const float*)d_in[0];
    const int*   src     = (const int*)d_in[1];
    const int*   dst     = (const int*)d_in[2];
    const float* W1  = (const float*)d_in[3];
    const float* b1  = (const float*)d_in[4];
    const float* W2  = (const float*)d_in[5];
    const float* b2  = (const float*)d_in[6];
    const float* W3  = (const float*)d_in[7];
    const float* b3  = (const float*)d_in[8];
    const float* W4  = (const float*)d_in[9];
    const float* b4  = (const float*)d_in[10];
    const float* ld1 = (const float*)d_in[11];
    const float* cW1 = (const float*)d_in[12];
    const float* cb1 = (const float*)d_in[13];
    const float* ld2 = (const float*)d_in[14];
    const float* cb2 = (const float*)d_in[16];
    const float* ld3 = (const float*)d_in[17];
    const float* cb3 = (const float*)d_in[19];

    float* out_logits = (float*)d_out;             // (N, 2)
    float* out_emb    = (float*)d_out + 2 * NN;    // (N, 64)

    const int mlp_smem = MLP_SMEM_FLOATS * 4;
    const int fin_smem = FIN_SMEM_FLOATS * 4;
    cudaFuncSetAttribute(mlp_kernel, cudaFuncAttributeMaxDynamicSharedMemorySize, mlp_smem);
    cudaFuncSetAttribute(final_kernel, cudaFuncAttributeMaxDynamicSharedMemorySize, fin_smem);

    zero_kernel<<<(NN * HD / 4 + 255) / 256, 256>>>();
    deg_kernel<<<EE / 256, 256>>>(dst);
    dinv_kernel<<<(NN + 255) / 256, 256>>>();
    mlp_kernel<<<NN / 32, 256, mlp_smem>>>(in_feat, W1, b1, W2, b2);
    scatter1_kernel<<<(EE * 16) / 256, 256>>>(src, dst);
    scatter2_kernel<<<(EE * 16) / 256, 256>>>(src, dst);
    final_kernel<<<NN / 32, 256, fin_smem>>>(cW1, cb1, cb2, cb3, ld1, ld2, ld3,
                                             W3, b3, W4, b4, out_logits, out_emb);
}

// round 2
// speedup vs baseline: 1.0575x; 1.0575x over previous
#include <cuda_runtime.h>

#define NN 100000
#define EE 1600000
#define HD 64

typedef unsigned long long ull;

// Scratch (device globals: no allocation allowed)
__device__ float g_deg[NN];
__device__ float g_dinv[NN];
__device__ float g_h[NN * HD];
__device__ float g_hs[NN * HD];   // h * dinv (pre-scaled for scatter1)
__device__ float g_agg[NN * HD];
__device__ float g_B[NN * HD];

// ---------------------------------------------------------------------------
// Packed f32x2 helpers (Blackwell FFMA2 path)
__device__ __forceinline__ ull pk2(float lo, float hi) {
    ull r; asm("mov.b64 %0, {%1,%2};" : "=l"(r) : "f"(lo), "f"(hi)); return r;
}
__device__ __forceinline__ void upk2(ull v, float& lo, float& hi) {
    asm("mov.b64 {%0,%1}, %2;" : "=f"(lo), "=f"(hi) : "l"(v));
}
__device__ __forceinline__ void fma2(ull& d, ull a, ull b) {
    asm("fma.rn.f32x2 %0, %1, %2, %0;" : "+l"(d) : "l"(a), "l"(b));
}

// ---------------------------------------------------------------------------
__global__ void zero_kernel() {
    int idx = blockIdx.x * blockDim.x + threadIdx.x;
    if (idx < NN * HD / 4) {
        ((float4*)g_agg)[idx] = make_float4(0.f, 0.f, 0.f, 0.f);
        ((float4*)g_B)[idx]   = make_float4(0.f, 0.f, 0.f, 0.f);
    }
    if (idx < NN) g_deg[idx] = 0.f;
}

__global__ void deg_kernel(const int* __restrict__ dst) {
    int e = blockIdx.x * 256 + threadIdx.x;
    if (e < EE) {
        float* p = g_deg + dst[e];
        asm volatile("red.global.add.f32 [%0], %1;" :: "l"(p), "f"(1.0f) : "memory");
    }
}

__global__ void dinv_kernel() {
    int n = blockIdx.x * 256 + threadIdx.x;
    if (n < NN) g_dinv[n] = rsqrtf(fmaxf(g_deg[n], 1.0f));
}

// ---------------------------------------------------------------------------
// Fused 2-layer MLP: h = relu(relu(X @ W1^T + b1) @ W2^T + b2); also hs = h*dinv
// 64 rows/block, 256 threads, each thread a 4x4 output tile, f32x2 FMA.
#define MS_W1   (64 * 133)               // sX  [64][133]
#define MS_W2   (MS_W1 + 128 * 68)       // sW1T [128][68]
#define MS_B1   (MS_W2 + 64 * 68)        // sW2T [64][68]
#define MS_B2   (MS_B1 + 64)
#define MLP_SMEM_FLOATS (MS_B2 + 64)

__global__ __launch_bounds__(256, 2) void mlp_kernel(
    const float* __restrict__ X, const float* __restrict__ W1,
    const float* __restrict__ b1, const float* __restrict__ W2,
    const float* __restrict__ b2)
{
    extern __shared__ float sm[];
    float* sX   = sm;           // [64][133] row-major (later aliased as sT)
    float* sW1T = sm + MS_W1;   // [128][68] W1^T
    float* sW2T = sm + MS_W2;   // [64][68]  W2^T
    float* sB1  = sm + MS_B1;
    float* sB2  = sm + MS_B2;

    int tid = threadIdx.x;
    int base = blockIdx.x * 64;

    // X rows -> sX (coalesced float4 reads, scalar smem stores)
    for (int i = tid; i < 2048; i += 256) {
        int row = i >> 5, k4 = (i & 31) << 2;
        float4 v = make_float4(0.f, 0.f, 0.f, 0.f);
        if (base + row < NN) v = *(const float4*)(X + (size_t)(base + row) * 128 + k4);
        float* p = sX + row * 133 + k4;
        p[0] = v.x; p[1] = v.y; p[2] = v.z; p[3] = v.w;
    }
    // W1^T, W2^T (coalesced scalar reads, strided stores: 4-way conflict, once)
    for (int i = tid; i < 8192; i += 256) {
        int j = i >> 7, k = i & 127;
        sW1T[k * 68 + j] = W1[i];
    }
    for (int i = tid; i < 4096; i += 256) {
        int j = i >> 6, k = i & 63;
        sW2T[k * 68 + j] = W2[i];
    }
    if (tid < 64) { sB1[tid] = b1[tid]; sB2[tid] = b2[tid]; }
    __syncthreads();

    int tx = tid & 15, ty = tid >> 4;
    int c0 = tx * 4, r0 = ty * 4;

    ull acc[4][2];
    {
        ull bi0 = pk2(sB1[c0], sB1[c0 + 1]);
        ull bi1 = pk2(sB1[c0 + 2], sB1[c0 + 3]);
#pragma unroll
        for (int r = 0; r < 4; r++) { acc[r][0] = bi0; acc[r][1] = bi1; }
    }
#pragma unroll 8
    for (int k = 0; k < 128; k++) {
        longlong2 wv = *(const longlong2*)(sW1T + k * 68 + c0);
        ull w0 = (ull)wv.x, w1 = (ull)wv.y;
        float x0 = sX[(r0 + 0) * 133 + k];
        float x1 = sX[(r0 + 1) * 133 + k];
        float x2 = sX[(r0 + 2) * 133 + k];
        float x3 = sX[(r0 + 3) * 133 + k];
        ull d0 = pk2(x0, x0), d1 = pk2(x1, x1), d2 = pk2(x2, x2), d3 = pk2(x3, x3);
        fma2(acc[0][0], d0, w0); fma2(acc[0][1], d0, w1);
        fma2(acc[1][0], d1, w0); fma2(acc[1][1], d1, w1);
        fma2(acc[2][0], d2, w0); fma2(acc[2][1], d2, w1);
        fma2(acc[3][0], d3, w0); fma2(acc[3][1], d3, w1);
    }
    __syncthreads();   // everyone done reading sX; reuse as sT
    float* sT = sX;
#pragma unroll
    for (int r = 0; r < 4; r++) {
        float v0, v1, v2, v3;
        upk2(acc[r][0], v0, v1); upk2(acc[r][1], v2, v3);
        float* p = sT + (r0 + r) * 133 + c0;
        p[0] = fmaxf(v0, 0.f); p[1] = fmaxf(v1, 0.f);
        p[2] = fmaxf(v2, 0.f); p[3] = fmaxf(v3, 0.f);
    }
    __syncthreads();

    {
        ull bi0 = pk2(sB2[c0], sB2[c0 + 1]);
        ull bi1 = pk2(sB2[c0 + 2], sB2[c0 + 3]);
#pragma unroll
        for (int r = 0; r < 4; r++) { acc[r][0] = bi0; acc[r][1] = bi1; }
    }
#pragma unroll 8
    for (int k = 0; k < 64; k++) {
        longlong2 wv = *(const longlong2*)(sW2T + k * 68 + c0);
        ull w0 = (ull)wv.x, w1 = (ull)wv.y;
        float x0 = sT[(r0 + 0) * 133 + k];
        float x1 = sT[(r0 + 1) * 133 + k];
        float x2 = sT[(r0 + 2) * 133 + k];
        float x3 = sT[(r0 + 3) * 133 + k];
        ull d0 = pk2(x0, x0), d1 = pk2(x1, x1), d2 = pk2(x2, x2), d3 = pk2(x3, x3);
        fma2(acc[0][0], d0, w0); fma2(acc[0][1], d0, w1);
        fma2(acc[1][0], d1, w0); fma2(acc[1][1], d1, w1);
        fma2(acc[2][0], d2, w0); fma2(acc[2][1], d2, w1);
        fma2(acc[3][0], d3, w0); fma2(acc[3][1], d3, w1);
    }
#pragma unroll
    for (int r = 0; r < 4; r++) {
        int n = base + r0 + r;
        if (n < NN) {
            float v0, v1, v2, v3;
            upk2(acc[r][0], v0, v1); upk2(acc[r][1], v2, v3);
            float4 o = make_float4(fmaxf(v0, 0.f), fmaxf(v1, 0.f),
                                   fmaxf(v2, 0.f), fmaxf(v3, 0.f));
            ((float4*)g_h)[n * 16 + tx] = o;
            float di = g_dinv[n];
            float4 os = make_float4(o.x * di, o.y * di, o.z * di, o.w * di);
            ((float4*)g_hs)[n * 16 + tx] = os;
        }
    }
}

// ---------------------------------------------------------------------------
// Scatter pass 1: agg += segsum(hs[src]) over dst (hs = h*dinv precomputed)
__global__ void scatter1_kernel(const int* __restrict__ src, const int* __restrict__ dst) {
    unsigned t = blockIdx.x * 256u + threadIdx.x;
    unsigned e = t >> 4;
    int c = t & 15;
    if (e >= EE) return;
    int lane = threadIdx.x & 31;
    int s = 0, d = 0;
    if ((lane & 15) == 0) { s = src[e]; d = dst[e]; }
    s = __shfl_sync(0xffffffffu, s, lane & 16);
    d = __shfl_sync(0xffffffffu, d, lane & 16);
    float4 v = ((const float4*)g_hs)[s * 16 + c];
    float4* p = ((float4*)g_agg) + d * 16 + c;
    asm volatile("red.global.add.v4.f32 [%0], {%1,%2,%3,%4};"
                 :: "l"(p), "f"(v.x), "f"(v.y), "f"(v.z), "f"(v.w) : "memory");
}

// Scatter pass 2: B += segsum((agg * dinv^2)[src]) over dst.
__global__ void scatter2_kernel(const int* __restrict__ src, const int* __restrict__ dst) {
    unsigned t = blockIdx.x * 256u + threadIdx.x;
    unsigned e = t >> 4;
    int c = t & 15;
    if (e >= EE) return;
    int lane = threadIdx.x & 31;
    int s = 0, d = 0;
    if ((lane & 15) == 0) { s = src[e]; d = dst[e]; }
    s = __shfl_sync(0xffffffffu, s, lane & 16);
    d = __shfl_sync(0xffffffffu, d, lane & 16);
    float di = g_dinv[s];
    float sc = di * di;
    float4 v = ((const float4*)g_agg)[s * 16 + c];
    v.x *= sc; v.y *= sc; v.z *= sc; v.w *= sc;
    float4* p = ((float4*)g_B) + d * 16 + c;
    asm volatile("red.global.add.v4.f32 [%0], {%1,%2,%3,%4};"
                 :: "l"(p), "f"(v.x), "f"(v.y), "f"(v.z), "f"(v.w) : "memory");
}

// ---------------------------------------------------------------------------
// Fused epilogue: 3 poly-convs (algebraically shared aggregates) + concat MLP head.
// 64 nodes/block, 256 threads, 4x4 register tiles, f32x2 FMA.
#define FS_W3   (64 * 68)                  // s_cw1T [64][68]
#define FS_HF   (FS_W3 + 192 * 68)         // s_w3T  [192][68]
#define FS_HS   (FS_HF + 64 * 197)         // s_hf   [64][197]
#define FS_LD   (FS_HS + 64 * 133)         // s_hs   [64][133] (aliased by s_emb [64][66])
#define FS_CB   (FS_LD + 9 * 64)
#define FS_B3   (FS_CB + 192)
#define FS_W4   (FS_B3 + 64)
#define FS_B4   (FS_W4 + 128)
#define FIN_SMEM_FLOATS (FS_B4 + 4)

__global__ __launch_bounds__(256, 1) void final_kernel(
    const float* __restrict__ cW1, const float* __restrict__ cb1,
    const float* __restrict__ cb2, const float* __restrict__ cb3,
    const float* __restrict__ ld1, const float* __restrict__ ld2,
    const float* __restrict__ ld3,
    const float* __restrict__ W3, const float* __restrict__ b3,
    const float* __restrict__ W4, const float* __restrict__ b4,
    float* __restrict__ out_logits, float* __restrict__ out_emb)
{
    extern __shared__ float sm[];
    float* s_cw1T = sm;            // [64][68]
    float* s_w3T  = sm + FS_W3;    // [192][68]
    float* s_hf   = sm + FS_HF;    // [64][197] concat features (row-major)
    float* s_hs   = sm + FS_HS;    // [64][133] h*ld1_0
    float* s_emb  = sm + FS_HS;    // [64][66]  (aliases s_hs; s_hs dead by phase 3)
    float* s_ld   = sm + FS_LD;    // [9][64]
    float* s_cb   = sm + FS_CB;    // [3][64]
    float* s_b3   = sm + FS_B3;
    float* s_w4   = sm + FS_W4;    // [2][64]
    float* s_b4   = sm + FS_B4;

    int tid = threadIdx.x;
    int base = blockIdx.x * 64;

    for (int i = tid; i < 4096; i += 256) {
        int j = i >> 6, k = i & 63;
        s_cw1T[k * 68 + j] = cW1[i];
    }
    for (int i = tid; i < 12288; i += 256) {
        int j = i / 192, k = i % 192;
        s_w3T[k * 68 + j] = W3[i];
    }
    if (tid < 64) {
        int j = tid;
#pragma unroll
        for (int r = 0; r < 3; r++) {
            s_ld[(0 + r) * 64 + j] = ld1[r * 64 + j];
            s_ld[(3 + r) * 64 + j] = ld2[r * 64 + j];
            s_ld[(6 + r) * 64 + j] = ld3[r * 64 + j];
        }
        s_cb[j] = cb1[j]; s_cb[64 + j] = cb2[j]; s_cb[128 + j] = cb3[j];
        s_b3[j] = b3[j];
        s_w4[j] = W4[j]; s_w4[64 + j] = W4[64 + j];
    }
    if (tid < 2) s_b4[tid] = b4[tid];
    __syncthreads();

    // Phase 1: elementwise poly-conv parts (coalesced global reads)
    {
        int j = tid & 63, gg = tid >> 6;     // 4 rows at a time
#pragma unroll 4
        for (int it = 0; it < 16; it++) {
            int rowl = it * 4 + gg;
            int n = base + rowl;
            float hv = 0.f, a = 0.f, Bv = 0.f, di = 1.f;
            if (n < NN) {
                hv = g_h[(size_t)n * 64 + j];
                a  = g_agg[(size_t)n * 64 + j];
                Bv = g_B[(size_t)n * 64 + j];
                di = g_dinv[n];
            }
            float gv = a * di;
            // conv1 theta (3,-3,0.75)
            float l1 = s_ld[1 * 64 + j], l2 = s_ld[2 * 64 + j];
            float f1 = hv - l1 * gv;
            float f2 = f1 - l2 * ((a - l1 * Bv) * di);
            s_hf[rowl * 197 + j] = s_cb[j] - 3.f * f1 + 0.75f * f2;   // e1 part
            // conv2 theta (0,3,-1.5)
            l1 = s_ld[4 * 64 + j]; l2 = s_ld[5 * 64 + j];
            f1 = hv - l1 * gv;
            f2 = f1 - l2 * ((a - l1 * Bv) * di);
            s_hf[rowl * 197 + 64 + j] = s_cb[64 + j] + 3.f * f1 - 1.5f * f2;
            // conv3 theta (0,0,0.75)
            l1 = s_ld[7 * 64 + j]; l2 = s_ld[8 * 64 + j];
            f1 = hv - l1 * gv;
            f2 = f1 - l2 * ((a - l1 * Bv) * di);
            s_hf[rowl * 197 + 128 + j] = s_cb[128 + j] + 0.75f * f2;
            s_hs[rowl * 133 + j] = hv * s_ld[0 * 64 + j];
        }
    }
    __syncthreads();

    int tx = tid & 15, ty = tid >> 4;
    int c0 = tx * 4, r0 = ty * 4;
    ull acc[4][2];

    // Phase 2: hf[:,0:64] += 3 * (h*ld1_0) @ cW1^T
#pragma unroll
    for (int r = 0; r < 4; r++) { acc[r][0] = 0ull; acc[r][1] = 0ull; }
#pragma unroll 8
    for (int k = 0; k < 64; k++) {
        longlong2 wv = *(const longlong2*)(s_cw1T + k * 68 + c0);
        ull w0 = (ull)wv.x, w1 = (ull)wv.y;
        float x0 = s_hs[(r0 + 0) * 133 + k];
        float x1 = s_hs[(r0 + 1) * 133 + k];
        float x2 = s_hs[(r0 + 2) * 133 + k];
        float x3 = s_hs[(r0 + 3) * 133 + k];
        ull d0 = pk2(x0, x0), d1 = pk2(x1, x1), d2 = pk2(x2, x2), d3 = pk2(x3, x3);
        fma2(acc[0][0], d0, w0); fma2(acc[0][1], d0, w1);
        fma2(acc[1][0], d1, w0); fma2(acc[1][1], d1, w1);
        fma2(acc[2][0], d2, w0); fma2(acc[2][1], d2, w1);
        fma2(acc[3][0], d3, w0); fma2(acc[3][1], d3, w1);
    }
#pragma unroll
    for (int r = 0; r < 4; r++) {
        float v0, v1, v2, v3;
        upk2(acc[r][0], v0, v1); upk2(acc[r][1], v2, v3);
        float* p = s_hf + (r0 + r) * 197 + c0;
        p[0] += 3.f * v0; p[1] += 3.f * v1; p[2] += 3.f * v2; p[3] += 3.f * v3;
    }
    __syncthreads();

    // Phase 3: emb = relu(hf @ W3^T + b3)
    {
        ull bi0 = pk2(s_b3[c0], s_b3[c0 + 1]);
        ull bi1 = pk2(s_b3[c0 + 2], s_b3[c0 + 3]);
#pragma unroll
        for (int r = 0; r < 4; r++) { acc[r][0] = bi0; acc[r][1] = bi1; }
    }
#pragma unroll 4
    for (int k = 0; k < 192; k++) {
        longlong2 wv = *(const longlong2*)(s_w3T + k * 68 + c0);
        ull w0 = (ull)wv.x, w1 = (ull)wv.y;
        float x0 = s_hf[(r0 + 0) * 197 + k];
        float x1 = s_hf[(r0 + 1) * 197 + k];
        float x2 = s_hf[(r0 + 2) * 197 + k];
        float x3 = s_hf[(r0 + 3) * 197 + k];
        ull d0 = pk2(x0, x0), d1 = pk2(x1, x1), d2 = pk2(x2, x2), d3 = pk2(x3, x3);
        fma2(acc[0][0], d0, w0); fma2(acc[0][1], d0, w1);
        fma2(acc[1][0], d1, w0); fma2(acc[1][1], d1, w1);
        fma2(acc[2][0], d2, w0); fma2(acc[2][1], d2, w1);
        fma2(acc[3][0], d3, w0); fma2(acc[3][1], d3, w1);
    }
#pragma unroll
    for (int r = 0; r < 4; r++) {
        int n = base + r0 + r;
        float v0, v1, v2, v3;
        upk2(acc[r][0], v0, v1); upk2(acc[r][1], v2, v3);
        float4 o = make_float4(fmaxf(v0, 0.f), fmaxf(v1, 0.f),
                               fmaxf(v2, 0.f), fmaxf(v3, 0.f));
        if (n < NN) ((float4*)out_emb)[n * 16 + tx] = o;
        float* p = s_emb + (r0 + r) * 66 + c0;
        p[0] = o.x; p[1] = o.y; p[2] = o.z; p[3] = o.w;
    }
    __syncthreads();

    // Phase 4: logits = emb @ W4^T + b4
    if (tid < 128) {
        int rowl = tid >> 1, c = tid & 1;
        int n = base + rowl;
        if (n < NN) {
            float a2 = s_b4[c];
            const float* er = s_emb + rowl * 66;
            const float* wr = s_w4 + c * 64;
#pragma unroll 8
            for (int k = 0; k < 64; k++) a2 += wr[k] * er[k];
            out_logits[n * 2 + c] = a2;
        }
    }
}

// ---------------------------------------------------------------------------
extern "C" void kernel_launch(void* const* d_in, const int* in_sizes, int n_in,
                              void* d_out, int out_size) {
    const float* in_feat = (const float*)d_in[0];
    const int*   src     = (const int*)d_in[1];
    const int*   dst     = (const int*)d_in[2];
    const float* W1  = (const float*)d_in[3];
    const float* b1  = (const float*)d_in[4];
    const float* W2  = (const float*)d_in[5];
    const float* b2  = (const float*)d_in[6];
    const float* W3  = (const float*)d_in[7];
    const float* b3  = (const float*)d_in[8];
    const float* W4  = (const float*)d_in[9];
    const float* b4  = (const float*)d_in[10];
    const float* ld1 = (const float*)d_in[11];
    const float* cW1 = (const float*)d_in[12];
    const float* cb1 = (const float*)d_in[13];
    const float* ld2 = (const float*)d_in[14];
    const float* cb2 = (const float*)d_in[16];
    const float* ld3 = (const float*)d_in[17];
    const float* cb3 = (const float*)d_in[19];

    float* out_logits = (float*)d_out;             // (N, 2)
    float* out_emb    = (float*)d_out + 2 * NN;    // (N, 64)

    const int mlp_smem = MLP_SMEM_FLOATS * 4;
    const int fin_smem = FIN_SMEM_FLOATS * 4;
    cudaFuncSetAttribute(mlp_kernel, cudaFuncAttributeMaxDynamicSharedMemorySize, mlp_smem);
    cudaFuncSetAttribute(final_kernel, cudaFuncAttributeMaxDynamicSharedMemorySize, fin_smem);

    const int nblk = (NN + 63) / 64;   // 1563

    zero_kernel<<<(NN * HD / 4 + 255) / 256, 256>>>();
    deg_kernel<<<EE / 256, 256>>>(dst);
    dinv_kernel<<<(NN + 255) / 256, 256>>>();
    mlp_kernel<<<nblk, 256, mlp_smem>>>(in_feat, W1, b1, W2, b2);
    scatter1_kernel<<<(EE * 16) / 256, 256>>>(src, dst);
    scatter2_kernel<<<(EE * 16) / 256, 256>>>(src, dst);
    final_kernel<<<nblk, 256, fin_smem>>>(cW1, cb1, cb2, cb3, ld1, ld2, ld3,
                                          W3, b3, W4, b4, out_logits, out_emb);
}

// round 3
// speedup vs baseline: 1.3255x; 1.2534x over previous
#include <cuda_runtime.h>

#define NN 100000
#define EE 1600000
#define HD 64
#define NB 391            // ceil(NN/256)

typedef unsigned long long ull;

// Scratch (device globals: no allocation allowed)
__device__ int   g_degi[NN];
__device__ int   g_off[NN + 1];
__device__ int   g_cursor[NN];
__device__ int   g_part[NB];
__device__ int   g_pp[NB];
__device__ int   g_esrc[EE];
__device__ float g_dinv[NN];
__device__ float g_h[NN * HD];
__device__ float g_hs[NN * HD];    // h * dinv
__device__ float g_agg[NN * HD];   // segsum(hs)
__device__ float g_aggs[NN * HD];  // agg * dinv^2
__device__ float g_B[NN * HD];     // segsum(aggs)

// ---------------------------------------------------------------------------
__device__ __forceinline__ void fma2(ull& d, ull a, ull b) {
    asm("fma.rn.f32x2 %0, %1, %2, %0;" : "+l"(d) : "l"(a), "l"(b));
}
__device__ __forceinline__ void upk2(ull v, float& lo, float& hi) {
    asm("mov.b64 {%0,%1}, %2;" : "=f"(lo), "=f"(hi) : "l"(v));
}
__device__ __forceinline__ ull lds2(const float* p) { return *(const ull*)p; }

// ---------------------------------------------------------------------------
__global__ void zero_deg_kernel() {
    int i = blockIdx.x * 256 + threadIdx.x;
    if (i < NN) g_degi[i] = 0;
}

__global__ void degi_kernel(const int* __restrict__ dst) {
    int e = blockIdx.x * 256 + threadIdx.x;
    if (e < EE) atomicAdd(&g_degi[dst[e]], 1);
}

// Block-level exclusive scan, phase 1
__global__ void scan1_kernel() {
    __shared__ int s[256];
    int t = threadIdx.x;
    int i = blockIdx.x * 256 + t;
    int v = (i < NN) ? g_degi[i] : 0;
    s[t] = v;
    __syncthreads();
#pragma unroll
    for (int d = 1; d < 256; d <<= 1) {
        int tv = (t >= d) ? s[t - d] : 0;
        __syncthreads();
        s[t] += tv;
        __syncthreads();
    }
    if (i < NN) g_off[i] = s[t] - v;           // local exclusive
    if (t == 255) g_part[blockIdx.x] = s[255]; // block total
}

// Phase 2: scan the block partials (single block)
__global__ void scan2_kernel() {
    __shared__ int s[512];
    int t = threadIdx.x;
    s[t] = (t < NB) ? g_part[t] : 0;
    __syncthreads();
#pragma unroll
    for (int d = 1; d < 512; d <<= 1) {
        int tv = (t >= d) ? s[t - d] : 0;
        __syncthreads();
        s[t] += tv;
        __syncthreads();
    }
    if (t < NB) g_pp[t] = (t == 0) ? 0 : s[t - 1];
}

// Phase 3: add block prefixes, init cursors, dinv
__global__ void scan3_kernel() {
    int i = blockIdx.x * 256 + threadIdx.x;
    if (i < NN) {
        int o = g_off[i] + g_pp[blockIdx.x];
        g_off[i] = o;
        g_cursor[i] = o;
        g_dinv[i] = rsqrtf(fmaxf((float)g_degi[i], 1.0f));
    }
    if (i == 0) g_off[NN] = EE;
}

// Fill CSR edge list (src indices grouped by dst)
__global__ void csr_fill_kernel(const int* __restrict__ src, const int* __restrict__ dst) {
    int e = blockIdx.x * 256 + threadIdx.x;
    if (e < EE) {
        int d = dst[e];
        int p = atomicAdd(&g_cursor[d], 1);
        g_esrc[p] = src[e];
    }
}

// ---------------------------------------------------------------------------
// Fused 2-layer MLP: h = relu(relu(X @ W1^T + b1) @ W2^T + b2); hs = h*dinv
// 64 rows/block, 256 threads, 4x4 register tiles, k-paired f32x2.
#define MS_W1   (64 * 65 * 2)                // sXp  [64][65] f2
#define MS_W2   (MS_W1 + 64 * 65 * 2)        // sW1p [64][65] f2
#define MS_B1   (MS_W2 + 64 * 33 * 2)        // sW2p [64][33] f2
#define MS_B2   (MS_B1 + 64)
#define MLP_SMEM_FLOATS (MS_B2 + 64)

__global__ __launch_bounds__(256, 2) void mlp_kernel(
    const float* __restrict__ X, const float* __restrict__ W1,
    const float* __restrict__ b1, const float* __restrict__ W2,
    const float* __restrict__ b2)
{
    extern __shared__ float sm[];
    float* sXp  = sm;            // [64][65] float2 (130 floats/row)
    float* sW1p = sm + MS_W1;    // [64][65] float2
    float* sW2p = sm + MS_W2;    // [64][33] float2
    float* sB1  = sm + MS_B1;
    float* sB2  = sm + MS_B2;

    int tid = threadIdx.x;
    int base = blockIdx.x * 64;

    // X rows: 64 rows x 32 float4
    for (int i = tid; i < 2048; i += 256) {
        int row = i >> 5, q = i & 31;
        float4 v = make_float4(0.f, 0.f, 0.f, 0.f);
        if (base + row < NN) v = *(const float4*)(X + (size_t)(base + row) * 128 + q * 4);
        float* p = sXp + row * 130 + q * 4;
        p[0] = v.x; p[1] = v.y; p[2] = v.z; p[3] = v.w;
    }
    // W1 [64][128]: same shape
    for (int i = tid; i < 2048; i += 256) {
        int j = i >> 5, q = i & 31;
        float4 v = *(const float4*)(W1 + j * 128 + q * 4);
        float* p = sW1p + j * 130 + q * 4;
        p[0] = v.x; p[1] = v.y; p[2] = v.z; p[3] = v.w;
    }
    // W2 [64][64]
    for (int i = tid; i < 1024; i += 256) {
        int j = i >> 4, q = i & 15;
        float4 v = *(const float4*)(W2 + j * 64 + q * 4);
        float* p = sW2p + j * 66 + q * 4;
        p[0] = v.x; p[1] = v.y; p[2] = v.z; p[3] = v.w;
    }
    if (tid < 64) { sB1[tid] = b1[tid]; sB2[tid] = b2[tid]; }
    __syncthreads();

    int tx = tid & 15, ty = tid >> 4;
    int r0 = ty * 4;

    ull acc[4][4];
#pragma unroll
    for (int r = 0; r < 4; r++)
#pragma unroll
        for (int c = 0; c < 4; c++) acc[r][c] = 0ull;

#pragma unroll 8
    for (int kp = 0; kp < 64; kp++) {
        ull w0 = lds2(sW1p + (tx     ) * 130 + kp * 2);
        ull w1 = lds2(sW1p + (tx + 16) * 130 + kp * 2);
        ull w2 = lds2(sW1p + (tx + 32) * 130 + kp * 2);
        ull w3 = lds2(sW1p + (tx + 48) * 130 + kp * 2);
        ull x0 = lds2(sXp + (r0 + 0) * 130 + kp * 2);
        ull x1 = lds2(sXp + (r0 + 1) * 130 + kp * 2);
        ull x2 = lds2(sXp + (r0 + 2) * 130 + kp * 2);
        ull x3 = lds2(sXp + (r0 + 3) * 130 + kp * 2);
        fma2(acc[0][0], x0, w0); fma2(acc[0][1], x0, w1); fma2(acc[0][2], x0, w2); fma2(acc[0][3], x0, w3);
        fma2(acc[1][0], x1, w0); fma2(acc[1][1], x1, w1); fma2(acc[1][2], x1, w2); fma2(acc[1][3], x1, w3);
        fma2(acc[2][0], x2, w0); fma2(acc[2][1], x2, w1); fma2(acc[2][2], x2, w2); fma2(acc[2][3], x2, w3);
        fma2(acc[3][0], x3, w0); fma2(acc[3][1], x3, w1); fma2(acc[3][2], x3, w2); fma2(acc[3][3], x3, w3);
    }
    __syncthreads();              // done reading sXp; reuse as sT [64][66]
    float* sT = sXp;
#pragma unroll
    for (int r = 0; r < 4; r++)
#pragma unroll
        for (int c = 0; c < 4; c++) {
            int j = tx + 16 * c;
            float lo, hi; upk2(acc[r][c], lo, hi);
            sT[(r0 + r) * 66 + j] = fmaxf(lo + hi + sB1[j], 0.f);
            acc[r][c] = 0ull;
        }
    __syncthreads();

#pragma unroll 8
    for (int kp = 0; kp < 32; kp++) {
        ull w0 = lds2(sW2p + (tx     ) * 66 + kp * 2);
        ull w1 = lds2(sW2p + (tx + 16) * 66 + kp * 2);
        ull w2 = lds2(sW2p + (tx + 32) * 66 + kp * 2);
        ull w3 = lds2(sW2p + (tx + 48) * 66 + kp * 2);
        ull x0 = lds2(sT + (r0 + 0) * 66 + kp * 2);
        ull x1 = lds2(sT + (r0 + 1) * 66 + kp * 2);
        ull x2 = lds2(sT + (r0 + 2) * 66 + kp * 2);
        ull x3 = lds2(sT + (r0 + 3) * 66 + kp * 2);
        fma2(acc[0][0], x0, w0); fma2(acc[0][1], x0, w1); fma2(acc[0][2], x0, w2); fma2(acc[0][3], x0, w3);
        fma2(acc[1][0], x1, w0); fma2(acc[1][1], x1, w1); fma2(acc[1][2], x1, w2); fma2(acc[1][3], x1, w3);
        fma2(acc[2][0], x2, w0); fma2(acc[2][1], x2, w1); fma2(acc[2][2], x2, w2); fma2(acc[2][3], x2, w3);
        fma2(acc[3][0], x3, w0); fma2(acc[3][1], x3, w1); fma2(acc[3][2], x3, w2); fma2(acc[3][3], x3, w3);
    }
#pragma unroll
    for (int r = 0; r < 4; r++) {
        int n = base + r0 + r;
        if (n < NN) {
            float di = g_dinv[n];
#pragma unroll
            for (int c = 0; c < 4; c++) {
                int j = tx + 16 * c;
                float lo, hi; upk2(acc[r][c], lo, hi);
                float v = fmaxf(lo + hi + sB2[j], 0.f);
                g_h[(size_t)n * 64 + j]  = v;
                g_hs[(size_t)n * 64 + j] = v * di;
            }
        }
    }
}

// ---------------------------------------------------------------------------
// CSR gather-sum passes (atomic-free). 16 lanes per node, float4 per lane.
__global__ void agg1_kernel() {
    int warp = (blockIdx.x * 256 + threadIdx.x) >> 5;
    int lane = threadIdx.x & 31;
    int half = lane >> 4;
    int c = lane & 15;
    int n = warp * 2 + half;
    bool valid = n < NN;
    int beg = valid ? g_off[n] : 0;
    int end = valid ? g_off[n + 1] : 0;
    float4 acc = make_float4(0.f, 0.f, 0.f, 0.f);
    for (int basei = 0;; basei += 16) {
        if (!__any_sync(0xffffffffu, beg + basei < end)) break;
        int idx = beg + basei + c;
        int s = (idx < end) ? g_esrc[idx] : -1;
#pragma unroll
        for (int jj = 0; jj < 16; jj++) {
            int sj = __shfl_sync(0xffffffffu, s, (half << 4) + jj);
            if (sj >= 0) {
                float4 v = ((const float4*)g_hs)[sj * 16 + c];
                acc.x += v.x; acc.y += v.y; acc.z += v.z; acc.w += v.w;
            }
        }
    }
    if (valid) {
        ((float4*)g_agg)[n * 16 + c] = acc;
        float di = g_dinv[n];
        float s2 = di * di;
        float4 a2 = make_float4(acc.x * s2, acc.y * s2, acc.z * s2, acc.w * s2);
        ((float4*)g_aggs)[n * 16 + c] = a2;
    }
}

__global__ void agg2_kernel() {
    int warp = (blockIdx.x * 256 + threadIdx.x) >> 5;
    int lane = threadIdx.x & 31;
    int half = lane >> 4;
    int c = lane & 15;
    int n = warp * 2 + half;
    bool valid = n < NN;
    int beg = valid ? g_off[n] : 0;
    int end = valid ? g_off[n + 1] : 0;
    float4 acc = make_float4(0.f, 0.f, 0.f, 0.f);
    for (int basei = 0;; basei += 16) {
        if (!__any_sync(0xffffffffu, beg + basei < end)) break;
        int idx = beg + basei + c;
        int s = (idx < end) ? g_esrc[idx] : -1;
#pragma unroll
        for (int jj = 0; jj < 16; jj++) {
            int sj = __shfl_sync(0xffffffffu, s, (half << 4) + jj);
            if (sj >= 0) {
                float4 v = ((const float4*)g_aggs)[sj * 16 + c];
                acc.x += v.x; acc.y += v.y; acc.z += v.z; acc.w += v.w;
            }
        }
    }
    if (valid) ((float4*)g_B)[n * 16 + c] = acc;
}

// ---------------------------------------------------------------------------
// Fused epilogue: 3 poly-convs + concat head. 64 nodes/block, k-paired f32x2.
#define FS_W3   (64 * 33 * 2)                    // s_cw1p [64][33] f2
#define FS_HF   (FS_W3 + 64 * 97 * 2)            // s_w3p  [64][97] f2
#define FS_HS   (FS_HF + 64 * 97 * 2)            // s_hf   [64][97] f2 (194 floats)
#define FS_LD   (FS_HS + 64 * 33 * 2)            // s_hs   [64][66] floats (= s_emb)
#define FS_CB   (FS_LD + 9 * 64)
#define FS_B3   (FS_CB + 192)
#define FS_W4   (FS_B3 + 64)
#define FS_B4   (FS_W4 + 128)
#define FIN_SMEM_FLOATS (FS_B4 + 4)

__global__ __launch_bounds__(256, 1) void final_kernel(
    const float* __restrict__ cW1, const float* __restrict__ cb1,
    const float* __restrict__ cb2, const float* __restrict__ cb3,
    const float* __restrict__ ld1, const float* __restrict__ ld2,
    const float* __restrict__ ld3,
    const float* __restrict__ W3, const float* __restrict__ b3,
    const float* __restrict__ W4, const float* __restrict__ b4,
    float* __restrict__ out_logits, float* __restrict__ out_emb)
{
    extern __shared__ float sm[];
    float* s_cw1p = sm;            // [64][66 floats]
    float* s_w3p  = sm + FS_W3;    // [64][194 floats]
    float* s_hf   = sm + FS_HF;    // [64][194 floats]
    float* s_hs   = sm + FS_HS;    // [64][66 floats], aliased by s_emb
    float* s_emb  = sm + FS_HS;
    float* s_ld   = sm + FS_LD;    // [9][64]
    float* s_cb   = sm + FS_CB;    // [3][64]
    float* s_b3   = sm + FS_B3;
    float* s_w4   = sm + FS_W4;    // [2][64]
    float* s_b4   = sm + FS_B4;

    int tid = threadIdx.x;
    int base = blockIdx.x * 64;

    // cW1 [64][64]
    for (int i = tid; i < 1024; i += 256) {
        int j = i >> 4, q = i & 15;
        float4 v = *(const float4*)(cW1 + j * 64 + q * 4);
        float* p = s_cw1p + j * 66 + q * 4;
        p[0] = v.x; p[1] = v.y; p[2] = v.z; p[3] = v.w;
    }
    // W3 [64][192]
    for (int i = tid; i < 3072; i += 256) {
        int j = i / 48, q = i % 48;
        float4 v = *(const float4*)(W3 + j * 192 + q * 4);
        float* p = s_w3p + j * 194 + q * 4;
        p[0] = v.x; p[1] = v.y; p[2] = v.z; p[3] = v.w;
    }
    if (tid < 64) {
        int j = tid;
#pragma unroll
        for (int r = 0; r < 3; r++) {
            s_ld[(0 + r) * 64 + j] = ld1[r * 64 + j];
            s_ld[(3 + r) * 64 + j] = ld2[r * 64 + j];
            s_ld[(6 + r) * 64 + j] = ld3[r * 64 + j];
        }
        s_cb[j] = cb1[j]; s_cb[64 + j] = cb2[j]; s_cb[128 + j] = cb3[j];
        s_b3[j] = b3[j];
        s_w4[j] = W4[j]; s_w4[64 + j] = W4[64 + j];
    }
    if (tid < 2) s_b4[tid] = b4[tid];
    __syncthreads();

    // Phase 1: elementwise poly-conv parts
    {
        int j = tid & 63, gg = tid >> 6;
#pragma unroll 4
        for (int it = 0; it < 16; it++) {
            int rowl = it * 4 + gg;
            int n = base + rowl;
            float hv = 0.f, a = 0.f, Bv = 0.f, di = 1.f;
            if (n < NN) {
                hv = g_h[(size_t)n * 64 + j];
                a  = g_agg[(size_t)n * 64 + j];
                Bv = g_B[(size_t)n * 64 + j];
                di = g_dinv[n];
            }
            float gv = a * di;
            float l1 = s_ld[1 * 64 + j], l2 = s_ld[2 * 64 + j];
            float f1 = hv - l1 * gv;
            float f2 = f1 - l2 * ((a - l1 * Bv) * di);
            s_hf[rowl * 194 + j] = s_cb[j] - 3.f * f1 + 0.75f * f2;
            l1 = s_ld[4 * 64 + j]; l2 = s_ld[5 * 64 + j];
            f1 = hv - l1 * gv;
            f2 = f1 - l2 * ((a - l1 * Bv) * di);
            s_hf[rowl * 194 + 64 + j] = s_cb[64 + j] + 3.f * f1 - 1.5f * f2;
            l1 = s_ld[7 * 64 + j]; l2 = s_ld[8 * 64 + j];
            f1 = hv - l1 * gv;
            f2 = f1 - l2 * ((a - l1 * Bv) * di);
            s_hf[rowl * 194 + 128 + j] = s_cb[128 + j] + 0.75f * f2;
            s_hs[rowl * 66 + j] = hv * s_ld[0 * 64 + j];
        }
    }
    __syncthreads();

    int tx = tid & 15, ty = tid >> 4;
    int r0 = ty * 4;
    ull acc[4][4];
#pragma unroll
    for (int r = 0; r < 4; r++)
#pragma unroll
        for (int c = 0; c < 4; c++) acc[r][c] = 0ull;

    // Phase 2: hf[:,0:64] += 3 * (h*ld1_0) @ cW1^T
#pragma unroll 8
    for (int kp = 0; kp < 32; kp++) {
        ull w0 = lds2(s_cw1p + (tx     ) * 66 + kp * 2);
        ull w1 = lds2(s_cw1p + (tx + 16) * 66 + kp * 2);
        ull w2 = lds2(s_cw1p + (tx + 32) * 66 + kp * 2);
        ull w3 = lds2(s_cw1p + (tx + 48) * 66 + kp * 2);
        ull x0 = lds2(s_hs + (r0 + 0) * 66 + kp * 2);
        ull x1 = lds2(s_hs + (r0 + 1) * 66 + kp * 2);
        ull x2 = lds2(s_hs + (r0 + 2) * 66 + kp * 2);
        ull x3 = lds2(s_hs + (r0 + 3) * 66 + kp * 2);
        fma2(acc[0][0], x0, w0); fma2(acc[0][1], x0, w1); fma2(acc[0][2], x0, w2); fma2(acc[0][3], x0, w3);
        fma2(acc[1][0], x1, w0); fma2(acc[1][1], x1, w1); fma2(acc[1][2], x1, w2); fma2(acc[1][3], x1, w3);
        fma2(acc[2][0], x2, w0); fma2(acc[2][1], x2, w1); fma2(acc[2][2], x2, w2); fma2(acc[2][3], x2, w3);
        fma2(acc[3][0], x3, w0); fma2(acc[3][1], x3, w1); fma2(acc[3][2], x3, w2); fma2(acc[3][3], x3, w3);
    }
#pragma unroll
    for (int r = 0; r < 4; r++)
#pragma unroll
        for (int c = 0; c < 4; c++) {
            int j = tx + 16 * c;
            float lo, hi; upk2(acc[r][c], lo, hi);
            s_hf[(r0 + r) * 194 + j] += 3.f * (lo + hi);
            acc[r][c] = 0ull;
        }
    __syncthreads();

    // Phase 3: emb = relu(hf @ W3^T + b3)
#pragma unroll 4
    for (int kp = 0; kp < 96; kp++) {
        ull w0 = lds2(s_w3p + (tx     ) * 194 + kp * 2);
        ull w1 = lds2(s_w3p + (tx + 16) * 194 + kp * 2);
        ull w2 = lds2(s_w3p + (tx + 32) * 194 + kp * 2);
        ull w3 = lds2(s_w3p + (tx + 48) * 194 + kp * 2);
        ull x0 = lds2(s_hf + (r0 + 0) * 194 + kp * 2);
        ull x1 = lds2(s_hf + (r0 + 1) * 194 + kp * 2);
        ull x2 = lds2(s_hf + (r0 + 2) * 194 + kp * 2);
        ull x3 = lds2(s_hf + (r0 + 3) * 194 + kp * 2);
        fma2(acc[0][0], x0, w0); fma2(acc[0][1], x0, w1); fma2(acc[0][2], x0, w2); fma2(acc[0][3], x0, w3);
        fma2(acc[1][0], x1, w0); fma2(acc[1][1], x1, w1); fma2(acc[1][2], x1, w2); fma2(acc[1][3], x1, w3);
        fma2(acc[2][0], x2, w0); fma2(acc[2][1], x2, w1); fma2(acc[2][2], x2, w2); fma2(acc[2][3], x2, w3);
        fma2(acc[3][0], x3, w0); fma2(acc[3][1], x3, w1); fma2(acc[3][2], x3, w2); fma2(acc[3][3], x3, w3);
    }
    __syncthreads();   // s_hs readers done (phase 2); safe to write s_emb alias
#pragma unroll
    for (int r = 0; r < 4; r++) {
        int n = base + r0 + r;
#pragma unroll
        for (int c = 0; c < 4; c++) {
            int j = tx + 16 * c;
            float lo, hi; upk2(acc[r][c], lo, hi);
            float em = fmaxf(lo + hi + s_b3[j], 0.f);
            s_emb[(r0 + r) * 66 + j] = em;
            if (n < NN) out_emb[(size_t)n * 64 + j] = em;
        }
    }
    __syncthreads();

    // Phase 4: logits = emb @ W4^T + b4
    if (tid < 128) {
        int rowl = tid >> 1, c = tid & 1;
        int n = base + rowl;
        if (n < NN) {
            float a2 = s_b4[c];
            const float* er = s_emb + rowl * 66;
            const float* wr = s_w4 + c * 64;
#pragma unroll 8
            for (int k = 0; k < 64; k++) a2 += wr[k] * er[k];
            out_logits[n * 2 + c] = a2;
        }
    }
}

// ---------------------------------------------------------------------------
extern "C" void kernel_launch(void* const* d_in, const int* in_sizes, int n_in,
                              void* d_out, int out_size) {
    const float* in_feat = (const float*)d_in[0];
    const int*   src     = (const int*)d_in[1];
    const int*   dst     = (const int*)d_in[2];
    const float* W1  = (const float*)d_in[3];
    const float* b1  = (const float*)d_in[4];
    const float* W2  = (const float*)d_in[5];
    const float* b2  = (const float*)d_in[6];
    const float* W3  = (const float*)d_in[7];
    const float* b3  = (const float*)d_in[8];
    const float* W4  = (const float*)d_in[9];
    const float* b4  = (const float*)d_in[10];
    const float* ld1 = (const float*)d_in[11];
    const float* cW1 = (const float*)d_in[12];
    const float* cb1 = (const float*)d_in[13];
    const float* ld2 = (const float*)d_in[14];
    const float* cb2 = (const float*)d_in[16];
    const float* ld3 = (const float*)d_in[17];
    const float* cb3 = (const float*)d_in[19];

    float* out_logits = (float*)d_out;             // (N, 2)
    float* out_emb    = (float*)d_out + 2 * NN;    // (N, 64)

    const int mlp_smem = MLP_SMEM_FLOATS * 4;
    const int fin_smem = FIN_SMEM_FLOATS * 4;
    cudaFuncSetAttribute(mlp_kernel, cudaFuncAttributeMaxDynamicSharedMemorySize, mlp_smem);
    cudaFuncSetAttribute(final_kernel, cudaFuncAttributeMaxDynamicSharedMemorySize, fin_smem);

    const int nblk = (NN + 63) / 64;   // 1563
    const int eblk = EE / 256;         // 6250

    zero_deg_kernel<<<NB, 256>>>();
    degi_kernel<<<eblk, 256>>>(dst);
    scan1_kernel<<<NB, 256>>>();
    scan2_kernel<<<1, 512>>>();
    scan3_kernel<<<NB, 256>>>();
    csr_fill_kernel<<<eblk, 256>>>(src, dst);
    mlp_kernel<<<nblk, 256, mlp_smem>>>(in_feat, W1, b1, W2, b2);
    agg1_kernel<<<(NN / 2 + 7) / 8, 256>>>();   // 2 nodes per warp, 8 warps/block
    agg2_kernel<<<(NN / 2 + 7) / 8, 256>>>();
    final_kernel<<<nblk, 256, fin_smem>>>(cW1, cb1, cb2, cb3, ld1, ld2, ld3,
                                          W3, b3, W4, b4, out_logits, out_emb);
}

// round 4
// speedup vs baseline: 1.3884x; 1.0474x over previous
#include <cuda_runtime.h>
#include <cuda_fp16.h>

#define NN 100000
#define EE 1600000
#define HD 64
#define NB 391            // ceil(NN/256)

typedef unsigned long long ull;

// Scratch (device globals: no allocation allowed)
__device__ int    g_degi[NN];
__device__ int    g_off[NN + 1];
__device__ int    g_cursor[NN];
__device__ int    g_part[NB];
__device__ int    g_pp[NB];
__device__ int    g_esrc[EE];
__device__ float  g_dinv[NN];
__device__ float  g_h[NN * HD];
__device__ __half g_hs[NN * HD];    // h * dinv   (fp16: non-negative summands)
__device__ float  g_agg[NN * HD];   // segsum(hs)
__device__ __half g_aggs[NN * HD];  // agg * dinv^2 (fp16)
__device__ float  g_B[NN * HD];     // segsum(aggs)

// ---------------------------------------------------------------------------
__device__ __forceinline__ void fma2(ull& d, ull a, ull b) {
    asm("fma.rn.f32x2 %0, %1, %2, %0;" : "+l"(d) : "l"(a), "l"(b));
}
__device__ __forceinline__ void upk2(ull v, float& lo, float& hi) {
    asm("mov.b64 {%0,%1}, %2;" : "=f"(lo), "=f"(hi) : "l"(v));
}
__device__ __forceinline__ ull lds2(const float* p) { return *(const ull*)p; }

// ---------------------------------------------------------------------------
__global__ void zero_deg_kernel() {
    int i = blockIdx.x * 256 + threadIdx.x;
    if (i < NN) g_degi[i] = 0;
}

__global__ void degi_kernel(const int* __restrict__ dst) {
    int e = blockIdx.x * 256 + threadIdx.x;
    if (e < EE) atomicAdd(&g_degi[dst[e]], 1);
}

__global__ void scan1_kernel() {
    __shared__ int s[256];
    int t = threadIdx.x;
    int i = blockIdx.x * 256 + t;
    int v = (i < NN) ? g_degi[i] : 0;
    s[t] = v;
    __syncthreads();
#pragma unroll
    for (int d = 1; d < 256; d <<= 1) {
        int tv = (t >= d) ? s[t - d] : 0;
        __syncthreads();
        s[t] += tv;
        __syncthreads();
    }
    if (i < NN) g_off[i] = s[t] - v;
    if (t == 255) g_part[blockIdx.x] = s[255];
}

__global__ void scan2_kernel() {
    __shared__ int s[512];
    int t = threadIdx.x;
    s[t] = (t < NB) ? g_part[t] : 0;
    __syncthreads();
#pragma unroll
    for (int d = 1; d < 512; d <<= 1) {
        int tv = (t >= d) ? s[t - d] : 0;
        __syncthreads();
        s[t] += tv;
        __syncthreads();
    }
    if (t < NB) g_pp[t] = (t == 0) ? 0 : s[t - 1];
}

__global__ void scan3_kernel() {
    int i = blockIdx.x * 256 + threadIdx.x;
    if (i < NN) {
        int o = g_off[i] + g_pp[blockIdx.x];
        g_off[i] = o;
        g_cursor[i] = o;
        g_dinv[i] = rsqrtf(fmaxf((float)g_degi[i], 1.0f));
    }
    if (i == 0) g_off[NN] = EE;
}

__global__ void csr_fill_kernel(const int* __restrict__ src, const int* __restrict__ dst) {
    int e = blockIdx.x * 256 + threadIdx.x;
    if (e < EE) {
        int d = dst[e];
        int p = atomicAdd(&g_cursor[d], 1);
        g_esrc[p] = src[e];
    }
}

// ---------------------------------------------------------------------------
// Fused 2-layer MLP: h = relu(relu(X @ W1^T + b1) @ W2^T + b2); hs = h*dinv (fp16)
// 64 rows/block, 512 threads, 2x4 register tiles, k-paired f32x2.
#define MS_W1   (64 * 65 * 2)                // sXp  [64][65] f2
#define MS_W2   (MS_W1 + 64 * 65 * 2)        // sW1p [64][65] f2
#define MS_B1   (MS_W2 + 64 * 33 * 2)        // sW2p [64][33] f2
#define MS_B2   (MS_B1 + 64)
#define MLP_SMEM_FLOATS (MS_B2 + 64)

__global__ __launch_bounds__(512, 2) void mlp_kernel(
    const float* __restrict__ X, const float* __restrict__ W1,
    const float* __restrict__ b1, const float* __restrict__ W2,
    const float* __restrict__ b2)
{
    extern __shared__ float sm[];
    float* sXp  = sm;            // [64][130 floats]
    float* sW1p = sm + MS_W1;    // [64][130 floats]
    float* sW2p = sm + MS_W2;    // [64][66 floats]
    float* sB1  = sm + MS_B1;
    float* sB2  = sm + MS_B2;

    int tid = threadIdx.x;
    int base = blockIdx.x * 64;

    for (int i = tid; i < 2048; i += 512) {
        int row = i >> 5, q = i & 31;
        float4 v = make_float4(0.f, 0.f, 0.f, 0.f);
        if (base + row < NN) v = *(const float4*)(X + (size_t)(base + row) * 128 + q * 4);
        float* p = sXp + row * 130 + q * 4;
        p[0] = v.x; p[1] = v.y; p[2] = v.z; p[3] = v.w;
    }
    for (int i = tid; i < 2048; i += 512) {
        int j = i >> 5, q = i & 31;
        float4 v = *(const float4*)(W1 + j * 128 + q * 4);
        float* p = sW1p + j * 130 + q * 4;
        p[0] = v.x; p[1] = v.y; p[2] = v.z; p[3] = v.w;
    }
    for (int i = tid; i < 1024; i += 512) {
        int j = i >> 4, q = i & 15;
        float4 v = *(const float4*)(W2 + j * 64 + q * 4);
        float* p = sW2p + j * 66 + q * 4;
        p[0] = v.x; p[1] = v.y; p[2] = v.z; p[3] = v.w;
    }
    if (tid < 64) { sB1[tid] = b1[tid]; sB2[tid] = b2[tid]; }
    __syncthreads();

    int tx = tid & 15, ty = tid >> 4;   // ty in [0,32)
    int r0 = ty * 2;

    ull acc[2][4];
#pragma unroll
    for (int r = 0; r < 2; r++)
#pragma unroll
        for (int c = 0; c < 4; c++) acc[r][c] = 0ull;

#pragma unroll 8
    for (int kp = 0; kp < 64; kp++) {
        ull w0 = lds2(sW1p + (tx     ) * 130 + kp * 2);
        ull w1 = lds2(sW1p + (tx + 16) * 130 + kp * 2);
        ull w2 = lds2(sW1p + (tx + 32) * 130 + kp * 2);
        ull w3 = lds2(sW1p + (tx + 48) * 130 + kp * 2);
        ull x0 = lds2(sXp + (r0 + 0) * 130 + kp * 2);
        ull x1 = lds2(sXp + (r0 + 1) * 130 + kp * 2);
        fma2(acc[0][0], x0, w0); fma2(acc[0][1], x0, w1); fma2(acc[0][2], x0, w2); fma2(acc[0][3], x0, w3);
        fma2(acc[1][0], x1, w0); fma2(acc[1][1], x1, w1); fma2(acc[1][2], x1, w2); fma2(acc[1][3], x1, w3);
    }
    __syncthreads();              // done reading sXp; reuse as sT [64][66]
    float* sT = sXp;
#pragma unroll
    for (int r = 0; r < 2; r++)
#pragma unroll
        for (int c = 0; c < 4; c++) {
            int j = tx + 16 * c;
            float lo, hi; upk2(acc[r][c], lo, hi);
            sT[(r0 + r) * 66 + j] = fmaxf(lo + hi + sB1[j], 0.f);
            acc[r][c] = 0ull;
        }
    __syncthreads();

#pragma unroll 8
    for (int kp = 0; kp < 32; kp++) {
        ull w0 = lds2(sW2p + (tx     ) * 66 + kp * 2);
        ull w1 = lds2(sW2p + (tx + 16) * 66 + kp * 2);
        ull w2 = lds2(sW2p + (tx + 32) * 66 + kp * 2);
        ull w3 = lds2(sW2p + (tx + 48) * 66 + kp * 2);
        ull x0 = lds2(sT + (r0 + 0) * 66 + kp * 2);
        ull x1 = lds2(sT + (r0 + 1) * 66 + kp * 2);
        fma2(acc[0][0], x0, w0); fma2(acc[0][1], x0, w1); fma2(acc[0][2], x0, w2); fma2(acc[0][3], x0, w3);
        fma2(acc[1][0], x1, w0); fma2(acc[1][1], x1, w1); fma2(acc[1][2], x1, w2); fma2(acc[1][3], x1, w3);
    }
#pragma unroll
    for (int r = 0; r < 2; r++) {
        int n = base + r0 + r;
        if (n < NN) {
            float di = g_dinv[n];
#pragma unroll
            for (int c = 0; c < 4; c++) {
                int j = tx + 16 * c;
                float lo, hi; upk2(acc[r][c], lo, hi);
                float v = fmaxf(lo + hi + sB2[j], 0.f);
                g_h[(size_t)n * 64 + j]  = v;
                g_hs[(size_t)n * 64 + j] = __float2half_rn(v * di);
            }
        }
    }
}

// ---------------------------------------------------------------------------
// CSR gather-sum passes (atomic-free). 16 lanes per node, 4 fp16 cols per lane.
__global__ void agg1_kernel() {
    int warp = (blockIdx.x * 256 + threadIdx.x) >> 5;
    int lane = threadIdx.x & 31;
    int half = lane >> 4;
    int c = lane & 15;
    int n = warp * 2 + half;
    bool valid = n < NN;
    int beg = valid ? g_off[n] : 0;
    int end = valid ? g_off[n + 1] : 0;
    float4 acc = make_float4(0.f, 0.f, 0.f, 0.f);
    const uint2* hsrc = (const uint2*)g_hs;
    for (int basei = 0;; basei += 16) {
        if (!__any_sync(0xffffffffu, beg + basei < end)) break;
        int idx = beg + basei + c;
        int s = (idx < end) ? g_esrc[idx] : -1;
#pragma unroll
        for (int jj = 0; jj < 16; jj++) {
            int sj = __shfl_sync(0xffffffffu, s, (half << 4) + jj);
            if (sj >= 0) {
                uint2 u = hsrc[sj * 16 + c];
                float2 f0 = __half22float2(*(__half2*)&u.x);
                float2 f1 = __half22float2(*(__half2*)&u.y);
                acc.x += f0.x; acc.y += f0.y; acc.z += f1.x; acc.w += f1.y;
            }
        }
    }
    if (valid) {
        ((float4*)g_agg)[n * 16 + c] = acc;
        float di = g_dinv[n];
        float s2 = di * di;
        __half2 h0 = __floats2half2_rn(acc.x * s2, acc.y * s2);
        __half2 h1 = __floats2half2_rn(acc.z * s2, acc.w * s2);
        uint2 u; u.x = *(unsigned*)&h0; u.y = *(unsigned*)&h1;
        ((uint2*)g_aggs)[n * 16 + c] = u;
    }
}

__global__ void agg2_kernel() {
    int warp = (blockIdx.x * 256 + threadIdx.x) >> 5;
    int lane = threadIdx.x & 31;
    int half = lane >> 4;
    int c = lane & 15;
    int n = warp * 2 + half;
    bool valid = n < NN;
    int beg = valid ? g_off[n] : 0;
    int end = valid ? g_off[n + 1] : 0;
    float4 acc = make_float4(0.f, 0.f, 0.f, 0.f);
    const uint2* hsrc = (const uint2*)g_aggs;
    for (int basei = 0;; basei += 16) {
        if (!__any_sync(0xffffffffu, beg + basei < end)) break;
        int idx = beg + basei + c;
        int s = (idx < end) ? g_esrc[idx] : -1;
#pragma unroll
        for (int jj = 0; jj < 16; jj++) {
            int sj = __shfl_sync(0xffffffffu, s, (half << 4) + jj);
            if (sj >= 0) {
                uint2 u = hsrc[sj * 16 + c];
                float2 f0 = __half22float2(*(__half2*)&u.x);
                float2 f1 = __half22float2(*(__half2*)&u.y);
                acc.x += f0.x; acc.y += f0.y; acc.z += f1.x; acc.w += f1.y;
            }
        }
    }
    if (valid) ((float4*)g_B)[n * 16 + c] = acc;
}

// ---------------------------------------------------------------------------
// Fused epilogue: 3 poly-convs + concat head. 64 nodes/block, 512 threads,
// 2x4 tiles, k-paired f32x2.
#define FS_W3   (64 * 33 * 2)                    // s_cw1p [64][66 floats]
#define FS_HF   (FS_W3 + 64 * 97 * 2)            // s_w3p  [64][194 floats]
#define FS_HS   (FS_HF + 64 * 97 * 2)            // s_hf   [64][194 floats]
#define FS_LD   (FS_HS + 64 * 33 * 2)            // s_hs   [64][66] (= s_emb)
#define FS_CB   (FS_LD + 9 * 64)
#define FS_B3   (FS_CB + 192)
#define FS_W4   (FS_B3 + 64)
#define FS_B4   (FS_W4 + 128)
#define FIN_SMEM_FLOATS (FS_B4 + 4)

__global__ __launch_bounds__(512, 1) void final_kernel(
    const float* __restrict__ cW1, const float* __restrict__ cb1,
    const float* __restrict__ cb2, const float* __restrict__ cb3,
    const float* __restrict__ ld1, const float* __restrict__ ld2,
    const float* __restrict__ ld3,
    const float* __restrict__ W3, const float* __restrict__ b3,
    const float* __restrict__ W4, const float* __restrict__ b4,
    float* __restrict__ out_logits, float* __restrict__ out_emb)
{
    extern __shared__ float sm[];
    float* s_cw1p = sm;            // [64][66]
    float* s_w3p  = sm + FS_W3;    // [64][194]
    float* s_hf   = sm + FS_HF;    // [64][194]
    float* s_hs   = sm + FS_HS;    // [64][66], aliased by s_emb
    float* s_emb  = sm + FS_HS;
    float* s_ld   = sm + FS_LD;    // [9][64]
    float* s_cb   = sm + FS_CB;    // [3][64]
    float* s_b3   = sm + FS_B3;
    float* s_w4   = sm + FS_W4;    // [2][64]
    float* s_b4   = sm + FS_B4;

    int tid = threadIdx.x;
    int base = blockIdx.x * 64;

    for (int i = tid; i < 1024; i += 512) {
        int j = i >> 4, q = i & 15;
        float4 v = *(const float4*)(cW1 + j * 64 + q * 4);
        float* p = s_cw1p + j * 66 + q * 4;
        p[0] = v.x; p[1] = v.y; p[2] = v.z; p[3] = v.w;
    }
    for (int i = tid; i < 3072; i += 512) {
        int j = i / 48, q = i % 48;
        float4 v = *(const float4*)(W3 + j * 192 + q * 4);
        float* p = s_w3p + j * 194 + q * 4;
        p[0] = v.x; p[1] = v.y; p[2] = v.z; p[3] = v.w;
    }
    if (tid < 64) {
        int j = tid;
#pragma unroll
        for (int r = 0; r < 3; r++) {
            s_ld[(0 + r) * 64 + j] = ld1[r * 64 + j];
            s_ld[(3 + r) * 64 + j] = ld2[r * 64 + j];
            s_ld[(6 + r) * 64 + j] = ld3[r * 64 + j];
        }
        s_cb[j] = cb1[j]; s_cb[64 + j] = cb2[j]; s_cb[128 + j] = cb3[j];
        s_b3[j] = b3[j];
        s_w4[j] = W4[j]; s_w4[64 + j] = W4[64 + j];
    }
    if (tid < 2) s_b4[tid] = b4[tid];
    __syncthreads();

    // Phase 1: elementwise poly-conv parts
    {
        int j = tid & 63, gg = tid >> 6;   // 8 row-groups
#pragma unroll 2
        for (int it = 0; it < 8; it++) {
            int rowl = it * 8 + gg;
            int n = base + rowl;
            float hv = 0.f, a = 0.f, Bv = 0.f, di = 1.f;
            if (n < NN) {
                hv = g_h[(size_t)n * 64 + j];
                a  = g_agg[(size_t)n * 64 + j];
                Bv = g_B[(size_t)n * 64 + j];
                di = g_dinv[n];
            }
            float gv = a * di;
            float l1 = s_ld[1 * 64 + j], l2 = s_ld[2 * 64 + j];
            float f1 = hv - l1 * gv;
            float f2 = f1 - l2 * ((a - l1 * Bv) * di);
            s_hf[rowl * 194 + j] = s_cb[j] - 3.f * f1 + 0.75f * f2;
            l1 = s_ld[4 * 64 + j]; l2 = s_ld[5 * 64 + j];
            f1 = hv - l1 * gv;
            f2 = f1 - l2 * ((a - l1 * Bv) * di);
            s_hf[rowl * 194 + 64 + j] = s_cb[64 + j] + 3.f * f1 - 1.5f * f2;
            l1 = s_ld[7 * 64 + j]; l2 = s_ld[8 * 64 + j];
            f1 = hv - l1 * gv;
            f2 = f1 - l2 * ((a - l1 * Bv) * di);
            s_hf[rowl * 194 + 128 + j] = s_cb[128 + j] + 0.75f * f2;
            s_hs[rowl * 66 + j] = hv * s_ld[0 * 64 + j];
        }
    }
    __syncthreads();

    int tx = tid & 15, ty = tid >> 4;   // ty in [0,32)
    int r0 = ty * 2;
    ull acc[2][4];
#pragma unroll
    for (int r = 0; r < 2; r++)
#pragma unroll
        for (int c = 0; c < 4; c++) acc[r][c] = 0ull;

    // Phase 2: hf[:,0:64] += 3 * (h*ld1_0) @ cW1^T
#pragma unroll 8
    for (int kp = 0; kp < 32; kp++) {
        ull w0 = lds2(s_cw1p + (tx     ) * 66 + kp * 2);
        ull w1 = lds2(s_cw1p + (tx + 16) * 66 + kp * 2);
        ull w2 = lds2(s_cw1p + (tx + 32) * 66 + kp * 2);
        ull w3 = lds2(s_cw1p + (tx + 48) * 66 + kp * 2);
        ull x0 = lds2(s_hs + (r0 + 0) * 66 + kp * 2);
        ull x1 = lds2(s_hs + (r0 + 1) * 66 + kp * 2);
        fma2(acc[0][0], x0, w0); fma2(acc[0][1], x0, w1); fma2(acc[0][2], x0, w2); fma2(acc[0][3], x0, w3);
        fma2(acc[1][0], x1, w0); fma2(acc[1][1], x1, w1); fma2(acc[1][2], x1, w2); fma2(acc[1][3], x1, w3);
    }
#pragma unroll
    for (int r = 0; r < 2; r++)
#pragma unroll
        for (int c = 0; c < 4; c++) {
            int j = tx + 16 * c;
            float lo, hi; upk2(acc[r][c], lo, hi);
            s_hf[(r0 + r) * 194 + j] += 3.f * (lo + hi);
            acc[r][c] = 0ull;
        }
    __syncthreads();

    // Phase 3: emb = relu(hf @ W3^T + b3)
#pragma unroll 4
    for (int kp = 0; kp < 96; kp++) {
        ull w0 = lds2(s_w3p + (tx     ) * 194 + kp * 2);
        ull w1 = lds2(s_w3p + (tx + 16) * 194 + kp * 2);
        ull w2 = lds2(s_w3p + (tx + 32) * 194 + kp * 2);
        ull w3 = lds2(s_w3p + (tx + 48) * 194 + kp * 2);
        ull x0 = lds2(s_hf + (r0 + 0) * 194 + kp * 2);
        ull x1 = lds2(s_hf + (r0 + 1) * 194 + kp * 2);
        fma2(acc[0][0], x0, w0); fma2(acc[0][1], x0, w1); fma2(acc[0][2], x0, w2); fma2(acc[0][3], x0, w3);
        fma2(acc[1][0], x1, w0); fma2(acc[1][1], x1, w1); fma2(acc[1][2], x1, w2); fma2(acc[1][3], x1, w3);
    }
    __syncthreads();   // s_hs readers done (phase 2); safe to write s_emb alias
#pragma unroll
    for (int r = 0; r < 2; r++) {
        int n = base + r0 + r;
#pragma unroll
        for (int c = 0; c < 4; c++) {
            int j = tx + 16 * c;
            float lo, hi; upk2(acc[r][c], lo, hi);
            float em = fmaxf(lo + hi + s_b3[j], 0.f);
            s_emb[(r0 + r) * 66 + j] = em;
            if (n < NN) out_emb[(size_t)n * 64 + j] = em;
        }
    }
    __syncthreads();

    // Phase 4: logits = emb @ W4^T + b4
    if (tid < 128) {
        int rowl = tid >> 1, c = tid & 1;
        int n = base + rowl;
        if (n < NN) {
            float a2 = s_b4[c];
            const float* er = s_emb + rowl * 66;
            const float* wr = s_w4 + c * 64;
#pragma unroll 8
            for (int k = 0; k < 64; k++) a2 += wr[k] * er[k];
            out_logits[n * 2 + c] = a2;
        }
    }
}

// ---------------------------------------------------------------------------
extern "C" void kernel_launch(void* const* d_in, const int* in_sizes, int n_in,
                              void* d_out, int out_size) {
    const float* in_feat = (const float*)d_in[0];
    const int*   src     = (const int*)d_in[1];
    const int*   dst     = (const int*)d_in[2];
    const float* W1  = (const float*)d_in[3];
    const float* b1  = (const float*)d_in[4];
    const float* W2  = (const float*)d_in[5];
    const float* b2  = (const float*)d_in[6];
    const float* W3  = (const float*)d_in[7];
    const float* b3  = (const float*)d_in[8];
    const float* W4  = (const float*)d_in[9];
    const float* b4  = (const float*)d_in[10];
    const float* ld1 = (const float*)d_in[11];
    const float* cW1 = (const float*)d_in[12];
    const float* cb1 = (const float*)d_in[13];
    const float* ld2 = (const float*)d_in[14];
    const float* cb2 = (const float*)d_in[16];
    const float* ld3 = (const float*)d_in[17];
    const float* cb3 = (const float*)d_in[19];

    float* out_logits = (float*)d_out;             // (N, 2)
    float* out_emb    = (float*)d_out + 2 * NN;    // (N, 64)

    const int mlp_smem = MLP_SMEM_FLOATS * 4;
    const int fin_smem = FIN_SMEM_FLOATS * 4;
    cudaFuncSetAttribute(mlp_kernel, cudaFuncAttributeMaxDynamicSharedMemorySize, mlp_smem);
    cudaFuncSetAttribute(final_kernel, cudaFuncAttributeMaxDynamicSharedMemorySize, fin_smem);

    const int nblk = (NN + 63) / 64;   // 1563
    const int eblk = EE / 256;         // 6250

    zero_deg_kernel<<<NB, 256>>>();
    degi_kernel<<<eblk, 256>>>(dst);
    scan1_kernel<<<NB, 256>>>();
    scan2_kernel<<<1, 512>>>();
    scan3_kernel<<<NB, 256>>>();
    csr_fill_kernel<<<eblk, 256>>>(src, dst);
    mlp_kernel<<<nblk, 512, mlp_smem>>>(in_feat, W1, b1, W2, b2);
    agg1_kernel<<<(NN / 2 + 7) / 8, 256>>>();
    agg2_kernel<<<(NN / 2 + 7) / 8, 256>>>();
    final_kernel<<<nblk, 512, fin_smem>>>(cW1, cb1, cb2, cb3, ld1, ld2, ld3,
                                          W3, b3, W4, b4, out_logits, out_emb);
}

// round 5
// speedup vs baseline: 2.3617x; 1.7010x over previous
#include <cuda_runtime.h>
#include <cuda_fp16.h>

#define NN 100000
#define EE 1600000
#define HD 64
#define NB 391            // ceil(NN/256)

typedef unsigned long long ull;
typedef unsigned int u32;

// Scratch (device globals: no allocation allowed)
__device__ int    g_degi[NN];
__device__ int    g_off[NN + 1];
__device__ int    g_cursor[NN];
__device__ int    g_part[NB];
__device__ int    g_pp[NB];
__device__ int    g_esrc[EE];
__device__ float  g_dinv[NN];
__device__ float  g_h[NN * HD];
__device__ __half g_hs[NN * HD];    // h * dinv   (fp16: non-negative summands)
__device__ float  g_agg[NN * HD];   // segsum(hs)
__device__ __half g_aggs[NN * HD];  // agg * dinv^2 (fp16)
__device__ float  g_B[NN * HD];     // segsum(aggs)

// ---------------------------------------------------------------------------
__device__ __forceinline__ void mma16816(float* c, u32 a0, u32 a1, u32 a2, u32 a3,
                                         u32 b0, u32 b1) {
    asm volatile(
        "mma.sync.aligned.m16n8k16.row.col.f32.f16.f16.f32 "
        "{%0,%1,%2,%3}, {%4,%5,%6,%7}, {%8,%9}, {%0,%1,%2,%3};"
        : "+f"(c[0]), "+f"(c[1]), "+f"(c[2]), "+f"(c[3])
        : "r"(a0), "r"(a1), "r"(a2), "r"(a3), "r"(b0), "r"(b1));
}

__device__ __forceinline__ void st4h(__half* p, float4 v) {
    *(__half2*)(p)     = __floats2half2_rn(v.x, v.y);
    *(__half2*)(p + 2) = __floats2half2_rn(v.z, v.w);
}

// ---------------------------------------------------------------------------
__global__ void zero_deg_kernel() {
    int i = blockIdx.x * 256 + threadIdx.x;
    if (i < NN) g_degi[i] = 0;
}

__global__ void degi_kernel(const int* __restrict__ dst) {
    int e = blockIdx.x * 256 + threadIdx.x;
    if (e < EE) atomicAdd(&g_degi[dst[e]], 1);
}

__global__ void scan1_kernel() {
    __shared__ int s[256];
    int t = threadIdx.x;
    int i = blockIdx.x * 256 + t;
    int v = (i < NN) ? g_degi[i] : 0;
    s[t] = v;
    __syncthreads();
#pragma unroll
    for (int d = 1; d < 256; d <<= 1) {
        int tv = (t >= d) ? s[t - d] : 0;
        __syncthreads();
        s[t] += tv;
        __syncthreads();
    }
    if (i < NN) g_off[i] = s[t] - v;
    if (t == 255) g_part[blockIdx.x] = s[255];
}

__global__ void scan2_kernel() {
    __shared__ int s[512];
    int t = threadIdx.x;
    s[t] = (t < NB) ? g_part[t] : 0;
    __syncthreads();
#pragma unroll
    for (int d = 1; d < 512; d <<= 1) {
        int tv = (t >= d) ? s[t - d] : 0;
        __syncthreads();
        s[t] += tv;
        __syncthreads();
    }
    if (t < NB) g_pp[t] = (t == 0) ? 0 : s[t - 1];
}

__global__ void scan3_kernel() {
    int i = blockIdx.x * 256 + threadIdx.x;
    if (i < NN) {
        int o = g_off[i] + g_pp[blockIdx.x];
        g_off[i] = o;
        g_cursor[i] = o;
        g_dinv[i] = rsqrtf(fmaxf((float)g_degi[i], 1.0f));
    }
    if (i == 0) g_off[NN] = EE;
}

__global__ void csr_fill_kernel(const int* __restrict__ src, const int* __restrict__ dst) {
    int e = blockIdx.x * 256 + threadIdx.x;
    if (e < EE) {
        int d = dst[e];
        int p = atomicAdd(&g_cursor[d], 1);
        g_esrc[p] = src[e];
    }
}

// ---------------------------------------------------------------------------
// Fused 2-layer MLP on tensor cores: h = relu(relu(X W1^T + b1) W2^T + b2)
// 64 rows/block, 256 threads (8 warps): warp = (mt 0..3, nt 0..1).
// Byte offsets into dynamic smem:
#define M_A    0                 // sA  half [64][136]  17408
#define M_W1   17408             // sW1 half [64][136]  17408
#define M_T    34816             // sT  half [64][72]    9216
#define M_W2   44032             // sW2 half [64][72]    9216
#define M_B1   53248             // float[64]
#define M_B2   53504             // float[64]
#define MLP_SMEM_BYTES 53760

__global__ __launch_bounds__(256) void mlp_kernel(
    const float* __restrict__ X, const float* __restrict__ W1,
    const float* __restrict__ b1, const float* __restrict__ W2,
    const float* __restrict__ b2)
{
    extern __shared__ char smc[];
    __half* sA  = (__half*)(smc + M_A);
    __half* sW1 = (__half*)(smc + M_W1);
    __half* sT  = (__half*)(smc + M_T);
    __half* sW2 = (__half*)(smc + M_W2);
    float*  sB1 = (float*)(smc + M_B1);
    float*  sB2 = (float*)(smc + M_B2);

    int tid = threadIdx.x;
    int base = blockIdx.x * 64;

    for (int i = tid; i < 2048; i += 256) {
        int row = i >> 5, q = i & 31;
        float4 v = make_float4(0.f, 0.f, 0.f, 0.f);
        if (base + row < NN) v = *(const float4*)(X + (size_t)(base + row) * 128 + q * 4);
        st4h(sA + row * 136 + q * 4, v);
    }
    for (int i = tid; i < 2048; i += 256) {
        int row = i >> 5, q = i & 31;
        st4h(sW1 + row * 136 + q * 4, *(const float4*)(W1 + row * 128 + q * 4));
    }
    for (int i = tid; i < 1024; i += 256) {
        int row = i >> 4, q = i & 15;
        st4h(sW2 + row * 72 + q * 4, *(const float4*)(W2 + row * 64 + q * 4));
    }
    if (tid < 64) { sB1[tid] = b1[tid]; sB2[tid] = b2[tid]; }
    __syncthreads();

    int wid = tid >> 5, lane = tid & 31;
    int g = lane >> 2, t2 = (lane & 3) * 2;
    int m0 = (wid & 3) * 16, n0 = (wid >> 2) * 32;

    float acc[4][4];
#pragma unroll
    for (int ns = 0; ns < 4; ns++)
#pragma unroll
        for (int i = 0; i < 4; i++) acc[ns][i] = 0.f;

    // Layer 1: k = 128
#pragma unroll
    for (int kt = 0; kt < 8; kt++) {
        const __half* pa = sA + (m0 + g) * 136 + kt * 16 + t2;
        u32 a0 = *(const u32*)(pa);
        u32 a1 = *(const u32*)(pa + 8 * 136);
        u32 a2 = *(const u32*)(pa + 8);
        u32 a3 = *(const u32*)(pa + 8 * 136 + 8);
#pragma unroll
        for (int ns = 0; ns < 4; ns++) {
            const __half* pb = sW1 + (n0 + ns * 8 + g) * 136 + kt * 16 + t2;
            mma16816(acc[ns], a0, a1, a2, a3, *(const u32*)pb, *(const u32*)(pb + 8));
        }
    }
#pragma unroll
    for (int ns = 0; ns < 4; ns++) {
        int j0 = n0 + ns * 8 + t2;
        float b0 = sB1[j0], b1v = sB1[j0 + 1];
        *(__half2*)(sT + (m0 + g) * 72 + j0) =
            __floats2half2_rn(fmaxf(acc[ns][0] + b0, 0.f), fmaxf(acc[ns][1] + b1v, 0.f));
        *(__half2*)(sT + (m0 + g + 8) * 72 + j0) =
            __floats2half2_rn(fmaxf(acc[ns][2] + b0, 0.f), fmaxf(acc[ns][3] + b1v, 0.f));
        acc[ns][0] = acc[ns][1] = acc[ns][2] = acc[ns][3] = 0.f;
    }
    __syncthreads();

    // Layer 2: k = 64
#pragma unroll
    for (int kt = 0; kt < 4; kt++) {
        const __half* pa = sT + (m0 + g) * 72 + kt * 16 + t2;
        u32 a0 = *(const u32*)(pa);
        u32 a1 = *(const u32*)(pa + 8 * 72);
        u32 a2 = *(const u32*)(pa + 8);
        u32 a3 = *(const u32*)(pa + 8 * 72 + 8);
#pragma unroll
        for (int ns = 0; ns < 4; ns++) {
            const __half* pb = sW2 + (n0 + ns * 8 + g) * 72 + kt * 16 + t2;
            mma16816(acc[ns], a0, a1, a2, a3, *(const u32*)pb, *(const u32*)(pb + 8));
        }
    }
    {
        int n1 = base + m0 + g, n2 = n1 + 8;
        float d1 = (n1 < NN) ? g_dinv[n1] : 0.f;
        float d2 = (n2 < NN) ? g_dinv[n2] : 0.f;
#pragma unroll
        for (int ns = 0; ns < 4; ns++) {
            int j0 = n0 + ns * 8 + t2;
            float b0 = sB2[j0], b1v = sB2[j0 + 1];
            if (n1 < NN) {
                float v0 = fmaxf(acc[ns][0] + b0, 0.f), v1 = fmaxf(acc[ns][1] + b1v, 0.f);
                *(float2*)(g_h + (size_t)n1 * 64 + j0) = make_float2(v0, v1);
                *(__half2*)(g_hs + (size_t)n1 * 64 + j0) = __floats2half2_rn(v0 * d1, v1 * d1);
            }
            if (n2 < NN) {
                float v0 = fmaxf(acc[ns][2] + b0, 0.f), v1 = fmaxf(acc[ns][3] + b1v, 0.f);
                *(float2*)(g_h + (size_t)n2 * 64 + j0) = make_float2(v0, v1);
                *(__half2*)(g_hs + (size_t)n2 * 64 + j0) = __floats2half2_rn(v0 * d2, v1 * d2);
            }
        }
    }
}

// ---------------------------------------------------------------------------
// CSR gather-sum passes (atomic-free). 16 lanes per node, 4 fp16 cols per lane.
__global__ void agg1_kernel() {
    int warp = (blockIdx.x * 256 + threadIdx.x) >> 5;
    int lane = threadIdx.x & 31;
    int half = lane >> 4;
    int c = lane & 15;
    int n = warp * 2 + half;
    bool valid = n < NN;
    int beg = valid ? g_off[n] : 0;
    int end = valid ? g_off[n + 1] : 0;
    float4 acc = make_float4(0.f, 0.f, 0.f, 0.f);
    const uint2* hsrc = (const uint2*)g_hs;
    for (int basei = 0;; basei += 16) {
        if (!__any_sync(0xffffffffu, beg + basei < end)) break;
        int idx = beg + basei + c;
        int s = (idx < end) ? g_esrc[idx] : -1;
#pragma unroll
        for (int jj = 0; jj < 16; jj++) {
            int sj = __shfl_sync(0xffffffffu, s, (half << 4) + jj);
            if (sj >= 0) {
                uint2 u = hsrc[sj * 16 + c];
                float2 f0 = __half22float2(*(__half2*)&u.x);
                float2 f1 = __half22float2(*(__half2*)&u.y);
                acc.x += f0.x; acc.y += f0.y; acc.z += f1.x; acc.w += f1.y;
            }
        }
    }
    if (valid) {
        ((float4*)g_agg)[n * 16 + c] = acc;
        float di = g_dinv[n];
        float s2 = di * di;
        __half2 h0 = __floats2half2_rn(acc.x * s2, acc.y * s2);
        __half2 h1 = __floats2half2_rn(acc.z * s2, acc.w * s2);
        uint2 u; u.x = *(unsigned*)&h0; u.y = *(unsigned*)&h1;
        ((uint2*)g_aggs)[n * 16 + c] = u;
    }
}

__global__ void agg2_kernel() {
    int warp = (blockIdx.x * 256 + threadIdx.x) >> 5;
    int lane = threadIdx.x & 31;
    int half = lane >> 4;
    int c = lane & 15;
    int n = warp * 2 + half;
    bool valid = n < NN;
    int beg = valid ? g_off[n] : 0;
    int end = valid ? g_off[n + 1] : 0;
    float4 acc = make_float4(0.f, 0.f, 0.f, 0.f);
    const uint2* hsrc = (const uint2*)g_aggs;
    for (int basei = 0;; basei += 16) {
        if (!__any_sync(0xffffffffu, beg + basei < end)) break;
        int idx = beg + basei + c;
        int s = (idx < end) ? g_esrc[idx] : -1;
#pragma unroll
        for (int jj = 0; jj < 16; jj++) {
            int sj = __shfl_sync(0xffffffffu, s, (half << 4) + jj);
            if (sj >= 0) {
                uint2 u = hsrc[sj * 16 + c];
                float2 f0 = __half22float2(*(__half2*)&u.x);
                float2 f1 = __half22float2(*(__half2*)&u.y);
                acc.x += f0.x; acc.y += f0.y; acc.z += f1.x; acc.w += f1.y;
            }
        }
    }
    if (valid) ((float4*)g_B)[n * 16 + c] = acc;
}

// ---------------------------------------------------------------------------
// Fused epilogue on tensor cores: 3 poly-convs + concat head.
// 64 nodes/block, 256 threads (8 warps).
#define F_CW1  0                 // half [64][72]    9216
#define F_W3   9216              // half [64][200]  25600
#define F_HF   34816             // half [64][200]  25600
#define F_HS   60416             // half [64][72]    9216
#define F_EMB  69632             // float [64][68]  17408
#define F_LD   87040             // float [9][64]    2304
#define F_CB   89344             // float [3][64]     768
#define F_B3   90112             // float [64]        256
#define F_W4   90368             // float [2][64]     512
#define F_B4   90880             // float [2]           8
#define FIN_SMEM_BYTES 90912

__global__ __launch_bounds__(256) void final_kernel(
    const float* __restrict__ cW1, const float* __restrict__ cb1,
    const float* __restrict__ cb2, const float* __restrict__ cb3,
    const float* __restrict__ ld1, const float* __restrict__ ld2,
    const float* __restrict__ ld3,
    const float* __restrict__ W3, const float* __restrict__ b3,
    const float* __restrict__ W4, const float* __restrict__ b4,
    float* __restrict__ out_logits, float* __restrict__ out_emb)
{
    extern __shared__ char smc[];
    __half* s_cw1 = (__half*)(smc + F_CW1);
    __half* s_w3  = (__half*)(smc + F_W3);
    __half* s_hf  = (__half*)(smc + F_HF);
    __half* s_hs  = (__half*)(smc + F_HS);
    float*  s_emb = (float*)(smc + F_EMB);
    float*  s_ld  = (float*)(smc + F_LD);
    float*  s_cb  = (float*)(smc + F_CB);
    float*  s_b3  = (float*)(smc + F_B3);
    float*  s_w4  = (float*)(smc + F_W4);
    float*  s_b4  = (float*)(smc + F_B4);

    int tid = threadIdx.x;
    int base = blockIdx.x * 64;

    for (int i = tid; i < 1024; i += 256) {
        int row = i >> 4, q = i & 15;
        st4h(s_cw1 + row * 72 + q * 4, *(const float4*)(cW1 + row * 64 + q * 4));
    }
    for (int i = tid; i < 3072; i += 256) {
        int row = i / 48, q = i % 48;
        st4h(s_w3 + row * 200 + q * 4, *(const float4*)(W3 + row * 192 + q * 4));
    }
    if (tid < 64) {
        int j = tid;
#pragma unroll
        for (int r = 0; r < 3; r++) {
            s_ld[(0 + r) * 64 + j] = ld1[r * 64 + j];
            s_ld[(3 + r) * 64 + j] = ld2[r * 64 + j];
            s_ld[(6 + r) * 64 + j] = ld3[r * 64 + j];
        }
        s_cb[j] = cb1[j]; s_cb[64 + j] = cb2[j]; s_cb[128 + j] = cb3[j];
        s_b3[j] = b3[j];
        s_w4[j] = W4[j]; s_w4[64 + j] = W4[64 + j];
    }
    if (tid < 2) s_b4[tid] = b4[tid];
    __syncthreads();

    // Phase 1: elementwise poly-conv parts -> s_hf (fp16), s_hs (fp16)
    {
        int j = tid & 63, gg = tid >> 6;
#pragma unroll 4
        for (int it = 0; it < 16; it++) {
            int rowl = it * 4 + gg;
            int n = base + rowl;
            float hv = 0.f, a = 0.f, Bv = 0.f, di = 1.f;
            if (n < NN) {
                hv = g_h[(size_t)n * 64 + j];
                a  = g_agg[(size_t)n * 64 + j];
                Bv = g_B[(size_t)n * 64 + j];
                di = g_dinv[n];
            }
            float gv = a * di;
            float l1 = s_ld[1 * 64 + j], l2 = s_ld[2 * 64 + j];
            float f1 = hv - l1 * gv;
            float f2 = f1 - l2 * ((a - l1 * Bv) * di);
            s_hf[rowl * 200 + j] = __float2half_rn(s_cb[j] - 3.f * f1 + 0.75f * f2);
            l1 = s_ld[4 * 64 + j]; l2 = s_ld[5 * 64 + j];
            f1 = hv - l1 * gv;
            f2 = f1 - l2 * ((a - l1 * Bv) * di);
            s_hf[rowl * 200 + 64 + j] = __float2half_rn(s_cb[64 + j] + 3.f * f1 - 1.5f * f2);
            l1 = s_ld[7 * 64 + j]; l2 = s_ld[8 * 64 + j];
            f1 = hv - l1 * gv;
            f2 = f1 - l2 * ((a - l1 * Bv) * di);
            s_hf[rowl * 200 + 128 + j] = __float2half_rn(s_cb[128 + j] + 0.75f * f2);
            s_hs[rowl * 72 + j] = __float2half_rn(hv * s_ld[0 * 64 + j]);
        }
    }
    __syncthreads();

    int wid = tid >> 5, lane = tid & 31;
    int g = lane >> 2, t2 = (lane & 3) * 2;
    int m0 = (wid & 3) * 16, n0 = (wid >> 2) * 32;

    float acc[4][4];
#pragma unroll
    for (int ns = 0; ns < 4; ns++)
#pragma unroll
        for (int i = 0; i < 4; i++) acc[ns][i] = 0.f;

    // Phase 2: hf[:,0:64] += 3 * (h*ld1_0) @ cW1^T   (k = 64)
#pragma unroll
    for (int kt = 0; kt < 4; kt++) {
        const __half* pa = s_hs + (m0 + g) * 72 + kt * 16 + t2;
        u32 a0 = *(const u32*)(pa);
        u32 a1 = *(const u32*)(pa + 8 * 72);
        u32 a2 = *(const u32*)(pa + 8);
        u32 a3 = *(const u32*)(pa + 8 * 72 + 8);
#pragma unroll
        for (int ns = 0; ns < 4; ns++) {
            const __half* pb = s_cw1 + (n0 + ns * 8 + g) * 72 + kt * 16 + t2;
            mma16816(acc[ns], a0, a1, a2, a3, *(const u32*)pb, *(const u32*)(pb + 8));
        }
    }
#pragma unroll
    for (int ns = 0; ns < 4; ns++) {
        int j0 = n0 + ns * 8 + t2;
        __half2* p1 = (__half2*)(s_hf + (m0 + g) * 200 + j0);
        float2 o1 = __half22float2(*p1);
        *p1 = __floats2half2_rn(o1.x + 3.f * acc[ns][0], o1.y + 3.f * acc[ns][1]);
        __half2* p2 = (__half2*)(s_hf + (m0 + g + 8) * 200 + j0);
        float2 o2 = __half22float2(*p2);
        *p2 = __floats2half2_rn(o2.x + 3.f * acc[ns][2], o2.y + 3.f * acc[ns][3]);
        acc[ns][0] = acc[ns][1] = acc[ns][2] = acc[ns][3] = 0.f;
    }
    __syncthreads();

    // Phase 3: emb = relu(hf @ W3^T + b3)   (k = 192)
#pragma unroll
    for (int kt = 0; kt < 12; kt++) {
        const __half* pa = s_hf + (m0 + g) * 200 + kt * 16 + t2;
        u32 a0 = *(const u32*)(pa);
        u32 a1 = *(const u32*)(pa + 8 * 200);
        u32 a2 = *(const u32*)(pa + 8);
        u32 a3 = *(const u32*)(pa + 8 * 200 + 8);
#pragma unroll
        for (int ns = 0; ns < 4; ns++) {
            const __half* pb = s_w3 + (n0 + ns * 8 + g) * 200 + kt * 16 + t2;
            mma16816(acc[ns], a0, a1, a2, a3, *(const u32*)pb, *(const u32*)(pb + 8));
        }
    }
    {
        int n1 = base + m0 + g, n2 = n1 + 8;
#pragma unroll
        for (int ns = 0; ns < 4; ns++) {
            int j0 = n0 + ns * 8 + t2;
            float b0 = s_b3[j0], b1v = s_b3[j0 + 1];
            float v0 = fmaxf(acc[ns][0] + b0, 0.f), v1 = fmaxf(acc[ns][1] + b1v, 0.f);
            float v2 = fmaxf(acc[ns][2] + b0, 0.f), v3 = fmaxf(acc[ns][3] + b1v, 0.f);
            s_emb[(m0 + g) * 68 + j0]     = v0;
            s_emb[(m0 + g) * 68 + j0 + 1] = v1;
            s_emb[(m0 + g + 8) * 68 + j0]     = v2;
            s_emb[(m0 + g + 8) * 68 + j0 + 1] = v3;
            if (n1 < NN) *(float2*)(out_emb + (size_t)n1 * 64 + j0) = make_float2(v0, v1);
            if (n2 < NN) *(float2*)(out_emb + (size_t)n2 * 64 + j0) = make_float2(v2, v3);
        }
    }
    __syncthreads();

    // Phase 4: logits = emb @ W4^T + b4
    if (tid < 128) {
        int rowl = tid >> 1, c = tid & 1;
        int n = base + rowl;
        if (n < NN) {
            float a2 = s_b4[c];
            const float* er = s_emb + rowl * 68;
            const float* wr = s_w4 + c * 64;
#pragma unroll 8
            for (int k = 0; k < 64; k++) a2 += wr[k] * er[k];
            out_logits[n * 2 + c] = a2;
        }
    }
}

// ---------------------------------------------------------------------------
extern "C" void kernel_launch(void* const* d_in, const int* in_sizes, int n_in,
                              void* d_out, int out_size) {
    const float* in_feat = (const float*)d_in[0];
    const int*   src     = (const int*)d_in[1];
    const int*   dst     = (const int*)d_in[2];
    const float* W1  = (const float*)d_in[3];
    const float* b1  = (const float*)d_in[4];
    const float* W2  = (const float*)d_in[5];
    const float* b2  = (const float*)d_in[6];
    const float* W3  = (const float*)d_in[7];
    const float* b3  = (const float*)d_in[8];
    const float* W4  = (const float*)d_in[9];
    const float* b4  = (const float*)d_in[10];
    const float* ld1 = (const float*)d_in[11];
    const float* cW1 = (const float*)d_in[12];
    const float* cb1 = (const float*)d_in[13];
    const float* ld2 = (const float*)d_in[14];
    const float* cb2 = (const float*)d_in[16];
    const float* ld3 = (const float*)d_in[17];
    const float* cb3 = (const float*)d_in[19];

    float* out_logits = (float*)d_out;             // (N, 2)
    float* out_emb    = (float*)d_out + 2 * NN;    // (N, 64)

    cudaFuncSetAttribute(mlp_kernel, cudaFuncAttributeMaxDynamicSharedMemorySize, MLP_SMEM_BYTES);
    cudaFuncSetAttribute(final_kernel, cudaFuncAttributeMaxDynamicSharedMemorySize, FIN_SMEM_BYTES);

    const int nblk = (NN + 63) / 64;   // 1563
    const int eblk = EE / 256;         // 6250

    zero_deg_kernel<<<NB, 256>>>();
    degi_kernel<<<eblk, 256>>>(dst);
    scan1_kernel<<<NB, 256>>>();
    scan2_kernel<<<1, 512>>>();
    scan3_kernel<<<NB, 256>>>();
    csr_fill_kernel<<<eblk, 256>>>(src, dst);
    mlp_kernel<<<nblk, 256, MLP_SMEM_BYTES>>>(in_feat, W1, b1, W2, b2);
    agg1_kernel<<<(NN / 2 + 7) / 8, 256>>>();
    agg2_kernel<<<(NN / 2 + 7) / 8, 256>>>();
    final_kernel<<<nblk, 256, FIN_SMEM_BYTES>>>(cW1, cb1, cb2, cb3, ld1, ld2, ld3,
                                                W3, b3, W4, b4, out_logits, out_emb);
}